// round 7
// baseline (speedup 1.0000x reference)
#include <cuda_runtime.h>
#include <cstdint>

#define NX 128
#define NU 64
#define ND 192
#define TH 2048
#define GB 32      // backward grid blocks (co-resident, 32 <= 148 SMs)
#define NT 256
#define RPB 6      // Q rows per block: 192/32

// ---------------- static device scratch (no allocations allowed) ----------------
__device__ __align__(16) float g_Ft[ND * NX];          // F^T, 192x128
__device__ __align__(16) float g_Vb[2][NX * NX];
__device__ __align__(16) float g_vb[2][NX];
__device__ __align__(16) float g_Q[ND * ND];
__device__ __align__(16) float g_q[ND];
__device__ __align__(16) float g_inv[NU * NU];
__device__ float g_Ks[(size_t)TH * NU * NX];           // 64 MB
__device__ float g_ks[TH * NU];
__device__ float g_Ms[(size_t)TH * NX * NX];           // 128 MB
__device__ float g_bs[TH * NX];
__device__ unsigned g_delta[TH];
__device__ unsigned g_vmax[TH];
__device__ int g_niters;
__device__ unsigned g_barcnt = 0;
__device__ unsigned g_bargen = 0;

// ---------------- grid barrier (generation-based, fenced) ----------------
__device__ __forceinline__ void gbar() {
    __syncthreads();
    if (threadIdx.x == 0) {
        __threadfence();
        volatile unsigned* vg = &g_bargen;
        unsigned gen = *vg;
        if (atomicAdd(&g_barcnt, 1u) == (unsigned)(GB - 1)) {
            g_barcnt = 0u;
            __threadfence();
            atomicAdd(&g_bargen, 1u);
        } else {
            while (*vg == gen) { __nanosleep(64); }
        }
        __threadfence();
    }
    __syncthreads();
}

// ---------------- setup ----------------
__global__ void __launch_bounds__(NT) k_setup(const float* __restrict__ F,
                                              const float* __restrict__ C,
                                              const float* __restrict__ c) {
    int idx = blockIdx.x * NT + threadIdx.x;
    if (idx < ND * NX) {
        int i = idx / NX, m = idx - i * NX;
        g_Ft[i * NX + m] = F[m * ND + i];
    }
    if (idx < NX * NX) {
        int i = idx >> 7, j = idx & 127;
        g_Vb[0][idx] = C[i * ND + j];
    }
    if (idx < NX) g_vb[0][idx] = c[idx];
    if (idx < TH) { g_delta[idx] = 0u; g_vmax[idx] = 0u; }
    if (idx == 0) g_niters = TH;
}

// ---------------- backward Riccati (persistent, 32 CTAs) ----------------
__global__ void __launch_bounds__(NT) k_backward(const float* __restrict__ F,
                                                 const float* __restrict__ f,
                                                 const float* __restrict__ C,
                                                 const float* __restrict__ c) {
    const int b = blockIdx.x, tid = threadIdx.x;

    __shared__ float ft2[2][NX];
    __shared__ float fv2[2][NX];
    __shared__ float qred[8];
    __shared__ float prA[64], prI[64], fsh[64];
    __shared__ float pivsh;
    __shared__ float rmax[8], rvmx[8];

    for (int it = 0; it < TH; ++it) {
        const int p = it & 1;
        const float* V  = g_Vb[p];
        const float* v  = g_vb[p];
        float* Vn = g_Vb[p ^ 1];
        float* vn = g_vb[p ^ 1];

        // ===== phase 1: this CTA's 6 rows of Q (and q) =====
        const int i0 = b * RPB;
        for (int pr = 0; pr < RPB; pr += 2) {
            const int ri = tid >> 7;     // which of the 2 rows
            const int m  = tid & 127;
            const int i  = i0 + pr + ri;
            ft2[ri][m] = g_Ft[i * NX + m];
            __syncthreads();
            // FV row: FV[i][m] = sum_k Ft[i][k] * V[k][m]
            float a0 = 0.f, a1 = 0.f, a2 = 0.f, a3 = 0.f;
            #pragma unroll 8
            for (int k = 0; k < NX; k += 4) {
                a0 += ft2[ri][k    ] * __ldcg(&V[(k    ) * NX + m]);
                a1 += ft2[ri][k + 1] * __ldcg(&V[(k + 1) * NX + m]);
                a2 += ft2[ri][k + 2] * __ldcg(&V[(k + 2) * NX + m]);
                a3 += ft2[ri][k + 3] * __ldcg(&V[(k + 3) * NX + m]);
            }
            float fv = (a0 + a1) + (a2 + a3);
            fv2[ri][m] = fv;
            // q partial: FV[i][m]*f[m] + Ft[i][m]*v[m]
            float pq = fv * f[m] + ft2[ri][m] * __ldcg(&v[m]);
            #pragma unroll
            for (int o = 16; o > 0; o >>= 1) pq += __shfl_down_sync(0xffffffffu, pq, o);
            if ((tid & 31) == 0) qred[tid >> 5] = pq;
            __syncthreads();
            if (tid < 2) {
                float s = qred[tid * 4] + qred[tid * 4 + 1] + qred[tid * 4 + 2] + qred[tid * 4 + 3];
                g_q[i0 + pr + tid] = c[i0 + pr + tid] + s;
            }
            // Q rows: Q[i][j] = C[i][j] + sum_m FV[i][m] * F[m][j]
            #pragma unroll
            for (int rr = 0; rr < 2; ++rr) {
                const int irow = i0 + pr + rr;
                if (tid < ND) {
                    float b0 = 0.f, b1 = 0.f, b2 = 0.f, b3 = 0.f;
                    #pragma unroll 8
                    for (int mm = 0; mm < NX; mm += 4) {
                        b0 += fv2[rr][mm    ] * F[(mm    ) * ND + tid];
                        b1 += fv2[rr][mm + 1] * F[(mm + 1) * ND + tid];
                        b2 += fv2[rr][mm + 2] * F[(mm + 2) * ND + tid];
                        b3 += fv2[rr][mm + 3] * F[(mm + 3) * ND + tid];
                    }
                    g_Q[irow * ND + tid] = C[irow * ND + tid] + (b0 + b1) + (b2 + b3);
                }
            }
            __syncthreads();
        }
        gbar();

        // ===== phase 2: CTA0 inverts Q_uu (64x64 SPD, register Gauss-Jordan) =====
        if (b == 0) {
            const int r = tid >> 2, q4 = tid & 3;   // row, column quarter (16 cols)
            float ar[16], vi[16];
            #pragma unroll
            for (int jj = 0; jj < 16; ++jj) {
                int col = q4 * 16 + jj;
                ar[jj] = __ldcg(&g_Q[(NX + r) * ND + NX + col]);
                vi[jj] = (col == r) ? 1.0f : 0.0f;
            }
            #pragma unroll
            for (int pv = 0; pv < 64; ++pv) {
                const int ps = pv >> 4, pj = pv & 15;
                if (r == pv && q4 == ps) pivsh = 1.0f / ar[pj];
                __syncthreads();
                const float pvv = pivsh;
                if (r == pv) {
                    #pragma unroll
                    for (int jj = 0; jj < 16; ++jj) {
                        ar[jj] *= pvv; vi[jj] *= pvv;
                        prA[q4 * 16 + jj] = ar[jj];
                        prI[q4 * 16 + jj] = vi[jj];
                    }
                }
                if (q4 == ps) fsh[r] = ar[pj];
                __syncthreads();
                if (r != pv) {
                    const float fr = fsh[r];
                    #pragma unroll
                    for (int jj = 0; jj < 16; ++jj) {
                        ar[jj] -= fr * prA[q4 * 16 + jj];
                        vi[jj] -= fr * prI[q4 * 16 + jj];
                    }
                }
                __syncthreads();
            }
            #pragma unroll
            for (int jj = 0; jj < 16; ++jj) g_inv[r * 64 + q4 * 16 + jj] = vi[jj];
        }
        gbar();

        // ===== phase 3: K = -inv @ Q_ux, k = -inv @ q_u =====
        {
            const int g = b * NT + tid;          // 0..8191 = 64x128
            const int u = g >> 7, xc = g & 127;
            float a0 = 0.f, a1 = 0.f, a2 = 0.f, a3 = 0.f;
            #pragma unroll 4
            for (int mm = 0; mm < NU; mm += 4) {
                a0 += __ldcg(&g_inv[u * NU + mm    ]) * __ldcg(&g_Q[(NX + mm    ) * ND + xc]);
                a1 += __ldcg(&g_inv[u * NU + mm + 1]) * __ldcg(&g_Q[(NX + mm + 1) * ND + xc]);
                a2 += __ldcg(&g_inv[u * NU + mm + 2]) * __ldcg(&g_Q[(NX + mm + 2) * ND + xc]);
                a3 += __ldcg(&g_inv[u * NU + mm + 3]) * __ldcg(&g_Q[(NX + mm + 3) * ND + xc]);
            }
            g_Ks[(size_t)it * (NU * NX) + g] = -((a0 + a1) + (a2 + a3));
            if (g < NU) {
                float s = 0.f;
                #pragma unroll 4
                for (int mm = 0; mm < NU; ++mm)
                    s += __ldcg(&g_inv[g * NU + mm]) * __ldcg(&g_q[NX + mm]);
                g_ks[it * NU + g] = -s;
            }
        }
        gbar();

        // ===== phase 4: V' = Q_xx + Q_xu K, v' = q_x + Q_xu k, M, b, delta =====
        {
            const float* Kit = g_Ks + (size_t)it * (NU * NX);
            float dmax = 0.f, vmx = 0.f;
            const int g = b * NT + tid;
            #pragma unroll
            for (int h = 0; h < 2; ++h) {
                const int e = g + h * (GB * NT);     // 0..16383 = 128x128
                const int i = e >> 7, j = e & 127;
                float a0 = 0.f, a1 = 0.f, m0 = 0.f, m1 = 0.f;
                #pragma unroll 4
                for (int u = 0; u < NU; u += 2) {
                    float k0 = __ldcg(&Kit[(u    ) * NX + j]);
                    float k1 = __ldcg(&Kit[(u + 1) * NX + j]);
                    a0 += __ldcg(&g_Q[i * ND + NX + u    ]) * k0;
                    a1 += __ldcg(&g_Q[i * ND + NX + u + 1]) * k1;
                    m0 += F[i * ND + NX + u    ] * k0;
                    m1 += F[i * ND + NX + u + 1] * k1;
                }
                float vnew = __ldcg(&g_Q[i * ND + j]) + (a0 + a1);
                Vn[e] = vnew;
                dmax = fmaxf(dmax, fabsf(vnew - __ldcg(&V[e])));
                vmx  = fmaxf(vmx, fabsf(vnew));
                g_Ms[(size_t)it * (NX * NX) + e] = F[i * ND + j] + (m0 + m1);
            }
            if (g < NX) {
                float s = 0.f, sb = 0.f;
                #pragma unroll 4
                for (int u = 0; u < NU; ++u) {
                    float kk = __ldcg(&g_ks[it * NU + u]);
                    s  += __ldcg(&g_Q[g * ND + NX + u]) * kk;
                    sb += F[g * ND + NX + u] * kk;
                }
                vn[g] = __ldcg(&g_q[g]) + s;
                g_bs[it * NX + g] = f[g] + sb;
            }
            // CTA reduce max
            #pragma unroll
            for (int o = 16; o > 0; o >>= 1) {
                dmax = fmaxf(dmax, __shfl_down_sync(0xffffffffu, dmax, o));
                vmx  = fmaxf(vmx,  __shfl_down_sync(0xffffffffu, vmx, o));
            }
            if ((tid & 31) == 0) { rmax[tid >> 5] = dmax; rvmx[tid >> 5] = vmx; }
            __syncthreads();
            if (tid == 0) {
                float d = rmax[0], vv = rvmx[0];
                #pragma unroll
                for (int w = 1; w < 8; ++w) { d = fmaxf(d, rmax[w]); vv = fmaxf(vv, rvmx[w]); }
                atomicMax(&g_delta[it], __float_as_uint(d));
                atomicMax(&g_vmax[it], __float_as_uint(vv));
            }
        }
        gbar();

        // ===== convergence check (uniform across grid) =====
        {
            float dd = __uint_as_float(__ldcg(&g_delta[it]));
            float vv = __uint_as_float(__ldcg(&g_vmax[it]));
            if (dd <= 1e-6f * vv) {
                if (b == 0 && tid == 0) g_niters = it + 1;
                break;
            }
        }
    }
}

// ---------------- sequential rollout: x' = M_r x + b_r (one CTA) ----------------
__global__ void __launch_bounds__(256) k_rollout(const float* __restrict__ x0,
                                                 float* __restrict__ out_states) {
    const int tid = threadIdx.x;
    const int row = tid & 127, half = tid >> 7;
    const int ni = g_niters;
    __shared__ float xs[NX];
    __shared__ float ps[256];

    float mreg[64];
    {
        const float* Mc = g_Ms + (size_t)(ni - 1) * (NX * NX) + row * NX + half * 64;
        #pragma unroll
        for (int j = 0; j < 64; j += 4) {
            float4 t4 = *(const float4*)(Mc + j);
            mreg[j] = t4.x; mreg[j + 1] = t4.y; mreg[j + 2] = t4.z; mreg[j + 3] = t4.w;
        }
    }
    float breg = g_bs[(ni - 1) * NX + row];

    if (tid < NX) { xs[tid] = x0[tid]; out_states[tid] = x0[tid]; }
    __syncthreads();

    const int tconv = TH - ni;     // t <= tconv uses converged gains
    for (int t = 0; t < TH; ++t) {
        if (t > tconv) {
            const int r = TH - 1 - t;
            const float* Mr = g_Ms + (size_t)r * (NX * NX) + row * NX + half * 64;
            #pragma unroll
            for (int j = 0; j < 64; j += 4) {
                float4 t4 = *(const float4*)(Mr + j);
                mreg[j] = t4.x; mreg[j + 1] = t4.y; mreg[j + 2] = t4.z; mreg[j + 3] = t4.w;
            }
            breg = g_bs[r * NX + row];
        }
        float a0 = 0.f, a1 = 0.f, a2 = 0.f, a3 = 0.f;
        #pragma unroll
        for (int j = 0; j < 64; j += 4) {
            a0 += mreg[j    ] * xs[half * 64 + j    ];
            a1 += mreg[j + 1] * xs[half * 64 + j + 1];
            a2 += mreg[j + 2] * xs[half * 64 + j + 2];
            a3 += mreg[j + 3] * xs[half * 64 + j + 3];
        }
        ps[tid] = (a0 + a1) + (a2 + a3);
        __syncthreads();
        if (half == 0) {
            float xn = ps[row] + ps[128 + row] + breg;
            xs[row] = xn;
            out_states[(size_t)(t + 1) * NX + row] = xn;
        }
        __syncthreads();
    }
}

// ---------------- parallel epilogue: us + costs ----------------
__global__ void __launch_bounds__(192) k_epilogue(const float* __restrict__ C,
                                                  const float* __restrict__ c,
                                                  const float* __restrict__ states,
                                                  float* __restrict__ us,
                                                  float* __restrict__ costs) {
    const int t = blockIdx.x, tid = threadIdx.x;
    const int ni = g_niters;
    __shared__ float zs[ND];
    __shared__ float red[192];

    if (tid < NX) zs[tid] = states[(size_t)t * NX + tid];
    else zs[tid] = 0.0f;
    __syncthreads();

    if (t < TH && tid < NU) {
        int r = TH - 1 - t; if (r > ni - 1) r = ni - 1;
        const float* Kr = g_Ks + (size_t)r * (NU * NX) + tid * NX;
        float a0 = 0.f, a1 = 0.f, a2 = 0.f, a3 = 0.f;
        #pragma unroll 8
        for (int j = 0; j < NX; j += 4) {
            a0 += Kr[j    ] * zs[j    ];
            a1 += Kr[j + 1] * zs[j + 1];
            a2 += Kr[j + 2] * zs[j + 2];
            a3 += Kr[j + 3] * zs[j + 3];
        }
        float u = g_ks[r * NU + tid] + (a0 + a1) + (a2 + a3);
        zs[NX + tid] = u;
        us[(size_t)t * NU + tid] = u;
    }
    __syncthreads();

    // cost = sum_j z_j * (0.5*(z^T C)_j + c_j)
    float a0 = 0.f, a1 = 0.f, a2 = 0.f, a3 = 0.f;
    #pragma unroll 8
    for (int i = 0; i < ND; i += 4) {
        a0 += zs[i    ] * C[(i    ) * ND + tid];
        a1 += zs[i + 1] * C[(i + 1) * ND + tid];
        a2 += zs[i + 2] * C[(i + 2) * ND + tid];
        a3 += zs[i + 3] * C[(i + 3) * ND + tid];
    }
    float cz = (a0 + a1) + (a2 + a3);
    red[tid] = zs[tid] * (0.5f * cz + c[tid]);
    __syncthreads();
    #pragma unroll
    for (int s = 96; s >= 6; s >>= 1) {
        if (tid < s) red[tid] += red[tid + s];
        __syncthreads();
    }
    if (tid == 0)
        costs[t] = red[0] + red[1] + red[2] + red[3] + red[4] + red[5];
}

// ---------------- launch ----------------
extern "C" void kernel_launch(void* const* d_in, const int* in_sizes, int n_in,
                              void* d_out, int out_size) {
    const float* F  = (const float*)d_in[0];
    const float* f  = (const float*)d_in[1];
    const float* C  = (const float*)d_in[2];
    const float* c  = (const float*)d_in[3];
    const float* x0 = (const float*)d_in[4];
    (void)in_sizes; (void)n_in; (void)out_size;

    float* out        = (float*)d_out;
    float* out_states = out;                                   // (TH+1)*NX
    float* out_us     = out + (size_t)(TH + 1) * NX;           // TH*NU
    float* out_costs  = out_us + (size_t)TH * NU;              // TH+1

    k_setup<<<96, NT>>>(F, C, c);
    k_backward<<<GB, NT>>>(F, f, C, c);
    k_rollout<<<1, 256>>>(x0, out_states);
    k_epilogue<<<TH + 1, 192>>>(C, c, out_states, out_us, out_costs);
}

// round 8
// speedup vs baseline: 1.5093x; 1.5093x over previous
#include <cuda_runtime.h>
#include <cstdint>

#define NX 128
#define NU 64
#define ND 192
#define TH 2048
#define GB 32
#define NT 256
#define RPB 6
#define SEG 16

__device__ __align__(16) float g_Ft[ND * NX];
__device__ __align__(16) float g_Vb[2][NX * NX];
__device__ __align__(16) float g_vb[2][NX];
__device__ __align__(16) float g_Q[ND * ND];
__device__ __align__(16) float g_q[ND];
__device__ __align__(16) float g_inv[NU * NU];
__device__ float g_Ks[(size_t)TH * NU * NX];
__device__ float g_ks[TH * NU];
__device__ float g_Ms[(size_t)TH * NX * NX];
__device__ float g_bs[TH * NX];
__device__ __align__(16) float g_P[2][NX * NX];   // (M^(2^k)) ping-pong
__device__ __align__(16) float g_pb[2][NX];       // matching affine part
__device__ unsigned g_delta[TH];
__device__ unsigned g_vmax[TH];
__device__ int g_niters;
__device__ unsigned g_barcnt = 0;
__device__ unsigned g_bargen = 0;

__device__ __forceinline__ void gbar() {
    __syncthreads();
    if (threadIdx.x == 0) {
        __threadfence();
        volatile unsigned* vg = &g_bargen;
        unsigned gen = *vg;
        if (atomicAdd(&g_barcnt, 1u) == (unsigned)(GB - 1)) {
            g_barcnt = 0u;
            __threadfence();
            atomicAdd(&g_bargen, 1u);
        } else {
            while (*vg == gen) {}
        }
        __threadfence();
    }
    __syncthreads();
}

__global__ void __launch_bounds__(NT) k_setup(const float* __restrict__ F,
                                              const float* __restrict__ C,
                                              const float* __restrict__ c) {
    int idx = blockIdx.x * NT + threadIdx.x;
    if (idx < ND * NX) {
        int i = idx / NX, m = idx - i * NX;
        g_Ft[i * NX + m] = F[m * ND + i];
    }
    if (idx < NX * NX) {
        int i = idx >> 7, j = idx & 127;
        g_Vb[0][idx] = C[i * ND + j];
    }
    if (idx < NX) g_vb[0][idx] = c[idx];
    if (idx < TH) { g_delta[idx] = 0u; g_vmax[idx] = 0u; }
    if (idx == 0) g_niters = TH;
}

// ---------------- backward Riccati (persistent, 32 CTAs) ----------------
__global__ void __launch_bounds__(NT) k_backward(const float* __restrict__ F,
                                                 const float* __restrict__ f,
                                                 const float* __restrict__ C,
                                                 const float* __restrict__ c) {
    const int b = blockIdx.x, tid = threadIdx.x;

    __shared__ float ft2[2][NX];
    __shared__ float fv2[2][NX];
    __shared__ float qred[8];
    __shared__ float prA[64], prI[64], fsh[64];
    __shared__ float pivsh;
    __shared__ float rmax[8], rvmx[8];

    for (int it = 0; it < TH; ++it) {
        const int p = it & 1;
        const float* V  = g_Vb[p];
        const float* v  = g_vb[p];
        float* Vn = g_Vb[p ^ 1];
        float* vn = g_vb[p ^ 1];

        // ===== phase 1: this CTA's 6 rows of Q (and q) =====
        const int i0 = b * RPB;
        for (int pr = 0; pr < RPB; pr += 2) {
            const int ri = tid >> 7;
            const int m  = tid & 127;
            const int i  = i0 + pr + ri;
            ft2[ri][m] = g_Ft[i * NX + m];
            __syncthreads();
            float a0 = 0.f, a1 = 0.f, a2 = 0.f, a3 = 0.f;
            #pragma unroll 8
            for (int k = 0; k < NX; k += 4) {
                a0 += ft2[ri][k    ] * __ldcg(&V[(k    ) * NX + m]);
                a1 += ft2[ri][k + 1] * __ldcg(&V[(k + 1) * NX + m]);
                a2 += ft2[ri][k + 2] * __ldcg(&V[(k + 2) * NX + m]);
                a3 += ft2[ri][k + 3] * __ldcg(&V[(k + 3) * NX + m]);
            }
            float fv = (a0 + a1) + (a2 + a3);
            fv2[ri][m] = fv;
            float pq = fv * f[m] + ft2[ri][m] * __ldcg(&v[m]);
            #pragma unroll
            for (int o = 16; o > 0; o >>= 1) pq += __shfl_down_sync(0xffffffffu, pq, o);
            if ((tid & 31) == 0) qred[tid >> 5] = pq;
            __syncthreads();
            if (tid < 2) {
                float s = qred[tid * 4] + qred[tid * 4 + 1] + qred[tid * 4 + 2] + qred[tid * 4 + 3];
                g_q[i0 + pr + tid] = c[i0 + pr + tid] + s;
            }
            #pragma unroll
            for (int rr = 0; rr < 2; ++rr) {
                const int irow = i0 + pr + rr;
                if (tid < ND) {
                    float b0 = 0.f, b1 = 0.f, b2 = 0.f, b3 = 0.f;
                    #pragma unroll 8
                    for (int mm = 0; mm < NX; mm += 4) {
                        b0 += fv2[rr][mm    ] * F[(mm    ) * ND + tid];
                        b1 += fv2[rr][mm + 1] * F[(mm + 1) * ND + tid];
                        b2 += fv2[rr][mm + 2] * F[(mm + 2) * ND + tid];
                        b3 += fv2[rr][mm + 3] * F[(mm + 3) * ND + tid];
                    }
                    g_Q[irow * ND + tid] = C[irow * ND + tid] + (b0 + b1) + (b2 + b3);
                }
            }
            __syncthreads();
        }
        gbar();

        // ===== phase 2: CTA0 inverts Q_uu (64x64 SPD, register Gauss-Jordan) =====
        if (b == 0) {
            const int r = tid >> 2, q4 = tid & 3;
            float ar[16], vi[16];
            #pragma unroll
            for (int jj = 0; jj < 16; ++jj) {
                int col = q4 * 16 + jj;
                ar[jj] = __ldcg(&g_Q[(NX + r) * ND + NX + col]);
                vi[jj] = (col == r) ? 1.0f : 0.0f;
            }
            #pragma unroll
            for (int pv = 0; pv < 64; ++pv) {
                const int ps = pv >> 4, pj = pv & 15;
                if (r == pv && q4 == ps) pivsh = 1.0f / ar[pj];
                __syncthreads();
                const float pvv = pivsh;
                if (r == pv) {
                    #pragma unroll
                    for (int jj = 0; jj < 16; ++jj) {
                        ar[jj] *= pvv; vi[jj] *= pvv;
                        prA[q4 * 16 + jj] = ar[jj];
                        prI[q4 * 16 + jj] = vi[jj];
                    }
                }
                if (q4 == ps) fsh[r] = ar[pj];
                __syncthreads();
                if (r != pv) {
                    const float fr = fsh[r];
                    #pragma unroll
                    for (int jj = 0; jj < 16; ++jj) {
                        ar[jj] -= fr * prA[q4 * 16 + jj];
                        vi[jj] -= fr * prI[q4 * 16 + jj];
                    }
                }
                __syncthreads();
            }
            #pragma unroll
            for (int jj = 0; jj < 16; ++jj) g_inv[r * 64 + q4 * 16 + jj] = vi[jj];
        }
        gbar();

        // ===== phase 3: K = -inv @ Q_ux, k = -inv @ q_u =====
        {
            const int g = b * NT + tid;
            const int u = g >> 7, xc = g & 127;
            float a0 = 0.f, a1 = 0.f, a2 = 0.f, a3 = 0.f;
            #pragma unroll 4
            for (int mm = 0; mm < NU; mm += 4) {
                a0 += __ldcg(&g_inv[u * NU + mm    ]) * __ldcg(&g_Q[(NX + mm    ) * ND + xc]);
                a1 += __ldcg(&g_inv[u * NU + mm + 1]) * __ldcg(&g_Q[(NX + mm + 1) * ND + xc]);
                a2 += __ldcg(&g_inv[u * NU + mm + 2]) * __ldcg(&g_Q[(NX + mm + 2) * ND + xc]);
                a3 += __ldcg(&g_inv[u * NU + mm + 3]) * __ldcg(&g_Q[(NX + mm + 3) * ND + xc]);
            }
            g_Ks[(size_t)it * (NU * NX) + g] = -((a0 + a1) + (a2 + a3));
            if (g < NU) {
                float s = 0.f;
                #pragma unroll 4
                for (int mm = 0; mm < NU; ++mm)
                    s += __ldcg(&g_inv[g * NU + mm]) * __ldcg(&g_q[NX + mm]);
                g_ks[it * NU + g] = -s;
            }
        }
        gbar();

        // ===== phase 4: V', v', M, b, delta =====
        {
            const float* Kit = g_Ks + (size_t)it * (NU * NX);
            float dmax = 0.f, vmx = 0.f;
            const int g = b * NT + tid;
            #pragma unroll
            for (int h = 0; h < 2; ++h) {
                const int e = g + h * (GB * NT);
                const int i = e >> 7, j = e & 127;
                float a0 = 0.f, a1 = 0.f, m0 = 0.f, m1 = 0.f;
                #pragma unroll 4
                for (int u = 0; u < NU; u += 2) {
                    float k0 = __ldcg(&Kit[(u    ) * NX + j]);
                    float k1 = __ldcg(&Kit[(u + 1) * NX + j]);
                    a0 += __ldcg(&g_Q[i * ND + NX + u    ]) * k0;
                    a1 += __ldcg(&g_Q[i * ND + NX + u + 1]) * k1;
                    m0 += F[i * ND + NX + u    ] * k0;
                    m1 += F[i * ND + NX + u + 1] * k1;
                }
                float vnew = __ldcg(&g_Q[i * ND + j]) + (a0 + a1);
                Vn[e] = vnew;
                dmax = fmaxf(dmax, fabsf(vnew - __ldcg(&V[e])));
                vmx  = fmaxf(vmx, fabsf(vnew));
                g_Ms[(size_t)it * (NX * NX) + e] = F[i * ND + j] + (m0 + m1);
            }
            if (g < NX) {
                float s = 0.f, sb = 0.f;
                #pragma unroll 4
                for (int u = 0; u < NU; ++u) {
                    float kk = __ldcg(&g_ks[it * NU + u]);
                    s  += __ldcg(&g_Q[g * ND + NX + u]) * kk;
                    sb += F[g * ND + NX + u] * kk;
                }
                vn[g] = __ldcg(&g_q[g]) + s;
                g_bs[it * NX + g] = f[g] + sb;
            }
            #pragma unroll
            for (int o = 16; o > 0; o >>= 1) {
                dmax = fmaxf(dmax, __shfl_down_sync(0xffffffffu, dmax, o));
                vmx  = fmaxf(vmx,  __shfl_down_sync(0xffffffffu, vmx, o));
            }
            if ((tid & 31) == 0) { rmax[tid >> 5] = dmax; rvmx[tid >> 5] = vmx; }
            __syncthreads();
            if (tid == 0) {
                float d = rmax[0], vv = rvmx[0];
                #pragma unroll
                for (int w = 1; w < 8; ++w) { d = fmaxf(d, rmax[w]); vv = fmaxf(vv, rvmx[w]); }
                atomicMax(&g_delta[it], __float_as_uint(d));
                atomicMax(&g_vmax[it], __float_as_uint(vv));
            }
        }
        gbar();

        {
            float dd = __uint_as_float(__ldcg(&g_delta[it]));
            float vv = __uint_as_float(__ldcg(&g_vmax[it]));
            if (dd <= 1e-6f * vv) {
                if (b == 0 && tid == 0) g_niters = it + 1;
                break;
            }
        }
    }
}

// ---------------- init (M_conv, b_conv) into power buffer 0 ----------------
__global__ void __launch_bounds__(256) k_initP() {
    const int ni = g_niters;
    int o = blockIdx.x * 256 + threadIdx.x;
    if (o < NX * NX) g_P[0][o] = g_Ms[(size_t)(ni - 1) * (NX * NX) + o];
    if (o < NX) g_pb[0][o] = g_bs[(ni - 1) * NX + o];
}

// ---------------- one affine squaring: (M,b) -> (M*M, M*b + b) ----------------
__global__ void __launch_bounds__(256) k_sq(int p) {
    const float* __restrict__ Ms = g_P[p];
    const float* __restrict__ bs = g_pb[p];
    float* Md = g_P[p ^ 1];
    float* bd = g_pb[p ^ 1];
    int o = blockIdx.x * 256 + threadIdx.x;
    if (o < NX * NX) {
        int r = o >> 7, cc = o & 127;
        float a0 = 0.f, a1 = 0.f, a2 = 0.f, a3 = 0.f;
        #pragma unroll 8
        for (int k = 0; k < NX; k += 4) {
            a0 += Ms[r * NX + k    ] * Ms[(k    ) * NX + cc];
            a1 += Ms[r * NX + k + 1] * Ms[(k + 1) * NX + cc];
            a2 += Ms[r * NX + k + 2] * Ms[(k + 2) * NX + cc];
            a3 += Ms[r * NX + k + 3] * Ms[(k + 3) * NX + cc];
        }
        Md[o] = (a0 + a1) + (a2 + a3);
    } else if (o < NX * NX + NX) {
        int r = o - NX * NX;
        float s = 0.f;
        #pragma unroll 8
        for (int k = 0; k < NX; ++k) s += Ms[r * NX + k] * bs[k];
        bd[r] = s + bs[r];
    }
}

// ---------------- segment heads (M^16 chain) + time-varying tail ----------------
__global__ void __launch_bounds__(256) k_heads(const float* __restrict__ x0,
                                               float* __restrict__ out_states) {
    const int tid = threadIdx.x;
    const int row = tid & 127, half = tid >> 7;
    const int ni = g_niters;
    const int tconv = TH - ni;
    const int NS = (tconv + 1) / SEG;     // heads s=0..NS
    __shared__ float xs[NX];
    __shared__ float ps[256];

    float mreg[64];
    // ---- load M^16 ----
    {
        const float* Mc = g_P[0] + row * NX + half * 64;
        #pragma unroll
        for (int j = 0; j < 64; j += 4) {
            float4 t4 = *(const float4*)(Mc + j);
            mreg[j] = t4.x; mreg[j + 1] = t4.y; mreg[j + 2] = t4.z; mreg[j + 3] = t4.w;
        }
    }
    float breg = g_pb[0][row];

    if (tid < NX) { xs[tid] = x0[tid]; out_states[tid] = x0[tid]; }
    __syncthreads();

    for (int s = 1; s <= NS; ++s) {
        float a0 = 0.f, a1 = 0.f, a2 = 0.f, a3 = 0.f;
        #pragma unroll
        for (int j = 0; j < 64; j += 4) {
            a0 += mreg[j    ] * xs[half * 64 + j    ];
            a1 += mreg[j + 1] * xs[half * 64 + j + 1];
            a2 += mreg[j + 2] * xs[half * 64 + j + 2];
            a3 += mreg[j + 3] * xs[half * 64 + j + 3];
        }
        ps[tid] = (a0 + a1) + (a2 + a3);
        __syncthreads();
        if (half == 0) {
            float xn = ps[row] + ps[128 + row] + breg;
            xs[row] = xn;
            out_states[(size_t)s * SEG * NX + row] = xn;
        }
        __syncthreads();
    }

    // ---- tail: t = NS*SEG .. TH-1 (switches to per-step M once t > tconv) ----
    {
        const float* Mc = g_Ms + (size_t)(ni - 1) * (NX * NX) + row * NX + half * 64;
        #pragma unroll
        for (int j = 0; j < 64; j += 4) {
            float4 t4 = *(const float4*)(Mc + j);
            mreg[j] = t4.x; mreg[j + 1] = t4.y; mreg[j + 2] = t4.z; mreg[j + 3] = t4.w;
        }
        breg = g_bs[(ni - 1) * NX + row];
    }
    for (int t = NS * SEG; t < TH; ++t) {
        if (t > tconv) {
            const int r = TH - 1 - t;
            const float* Mr = g_Ms + (size_t)r * (NX * NX) + row * NX + half * 64;
            #pragma unroll
            for (int j = 0; j < 64; j += 4) {
                float4 t4 = *(const float4*)(Mr + j);
                mreg[j] = t4.x; mreg[j + 1] = t4.y; mreg[j + 2] = t4.z; mreg[j + 3] = t4.w;
            }
            breg = g_bs[r * NX + row];
        }
        float a0 = 0.f, a1 = 0.f, a2 = 0.f, a3 = 0.f;
        #pragma unroll
        for (int j = 0; j < 64; j += 4) {
            a0 += mreg[j    ] * xs[half * 64 + j    ];
            a1 += mreg[j + 1] * xs[half * 64 + j + 1];
            a2 += mreg[j + 2] * xs[half * 64 + j + 2];
            a3 += mreg[j + 3] * xs[half * 64 + j + 3];
        }
        ps[tid] = (a0 + a1) + (a2 + a3);
        __syncthreads();
        if (half == 0) {
            float xn = ps[row] + ps[128 + row] + breg;
            xs[row] = xn;
            out_states[(size_t)(t + 1) * NX + row] = xn;
        }
        __syncthreads();
    }
}

// ---------------- parallel segment fill (15 interior states per segment) ----------------
__global__ void __launch_bounds__(256) k_fill(float* __restrict__ out_states) {
    const int s = blockIdx.x;
    const int tid = threadIdx.x;
    const int row = tid & 127, half = tid >> 7;
    const int ni = g_niters;
    const int tconv = TH - ni;
    const int NS = (tconv + 1) / SEG;
    if (s >= NS) return;
    __shared__ float xs[NX];
    __shared__ float ps[256];

    float mreg[64];
    {
        const float* Mc = g_Ms + (size_t)(ni - 1) * (NX * NX) + row * NX + half * 64;
        #pragma unroll
        for (int j = 0; j < 64; j += 4) {
            float4 t4 = *(const float4*)(Mc + j);
            mreg[j] = t4.x; mreg[j + 1] = t4.y; mreg[j + 2] = t4.z; mreg[j + 3] = t4.w;
        }
    }
    float breg = g_bs[(ni - 1) * NX + row];

    if (tid < NX) xs[tid] = out_states[(size_t)s * SEG * NX + tid];
    __syncthreads();

    #pragma unroll 1
    for (int j2 = 1; j2 < SEG; ++j2) {
        float a0 = 0.f, a1 = 0.f, a2 = 0.f, a3 = 0.f;
        #pragma unroll
        for (int j = 0; j < 64; j += 4) {
            a0 += mreg[j    ] * xs[half * 64 + j    ];
            a1 += mreg[j + 1] * xs[half * 64 + j + 1];
            a2 += mreg[j + 2] * xs[half * 64 + j + 2];
            a3 += mreg[j + 3] * xs[half * 64 + j + 3];
        }
        ps[tid] = (a0 + a1) + (a2 + a3);
        __syncthreads();
        if (half == 0) {
            float xn = ps[row] + ps[128 + row] + breg;
            xs[row] = xn;
            out_states[(size_t)(s * SEG + j2) * NX + row] = xn;
        }
        __syncthreads();
    }
}

// ---------------- epilogue: 4 timesteps per block ----------------
__global__ void __launch_bounds__(192) k_epilogue(const float* __restrict__ C,
                                                  const float* __restrict__ c,
                                                  const float* __restrict__ states,
                                                  float* __restrict__ us,
                                                  float* __restrict__ costs) {
    const int t0 = blockIdx.x * 4, tid = threadIdx.x;
    const int ni = g_niters;
    __shared__ float zs[4][ND];
    __shared__ float red[192];

    #pragma unroll
    for (int k = 0; k < 4; ++k) {
        int t = t0 + k;
        if (tid < NX) zs[k][tid] = (t <= TH) ? states[(size_t)t * NX + tid] : 0.0f;
        else zs[k][tid] = 0.0f;
    }
    __syncthreads();

    if (tid < NU) {
        #pragma unroll
        for (int k = 0; k < 4; ++k) {
            int t = t0 + k;
            if (t < TH) {
                int r = TH - 1 - t; if (r > ni - 1) r = ni - 1;
                const float* Kr = g_Ks + (size_t)r * (NU * NX) + tid * NX;
                float a0 = 0.f, a1 = 0.f, a2 = 0.f, a3 = 0.f;
                #pragma unroll 8
                for (int j = 0; j < NX; j += 4) {
                    a0 += Kr[j    ] * zs[k][j    ];
                    a1 += Kr[j + 1] * zs[k][j + 1];
                    a2 += Kr[j + 2] * zs[k][j + 2];
                    a3 += Kr[j + 3] * zs[k][j + 3];
                }
                float u = g_ks[r * NU + tid] + (a0 + a1) + (a2 + a3);
                zs[k][NX + tid] = u;
                us[(size_t)t * NU + tid] = u;
            }
        }
    }
    __syncthreads();

    float cz0 = 0.f, cz1 = 0.f, cz2 = 0.f, cz3 = 0.f;
    #pragma unroll 4
    for (int i = 0; i < ND; ++i) {
        float Cv = C[i * ND + tid];
        cz0 += zs[0][i] * Cv;
        cz1 += zs[1][i] * Cv;
        cz2 += zs[2][i] * Cv;
        cz3 += zs[3][i] * Cv;
    }
    const float cv = c[tid];
    float val[4];
    val[0] = zs[0][tid] * (0.5f * cz0 + cv);
    val[1] = zs[1][tid] * (0.5f * cz1 + cv);
    val[2] = zs[2][tid] * (0.5f * cz2 + cv);
    val[3] = zs[3][tid] * (0.5f * cz3 + cv);

    #pragma unroll
    for (int k = 0; k < 4; ++k) {
        __syncthreads();
        red[tid] = val[k];
        __syncthreads();
        #pragma unroll
        for (int s = 96; s >= 6; s >>= 1) {
            if (tid < s) red[tid] += red[tid + s];
            __syncthreads();
        }
        int t = t0 + k;
        if (tid == 0 && t <= TH)
            costs[t] = red[0] + red[1] + red[2] + red[3] + red[4] + red[5];
    }
}

// ---------------- launch ----------------
extern "C" void kernel_launch(void* const* d_in, const int* in_sizes, int n_in,
                              void* d_out, int out_size) {
    const float* F  = (const float*)d_in[0];
    const float* f  = (const float*)d_in[1];
    const float* C  = (const float*)d_in[2];
    const float* c  = (const float*)d_in[3];
    const float* x0 = (const float*)d_in[4];
    (void)in_sizes; (void)n_in; (void)out_size;

    float* out        = (float*)d_out;
    float* out_states = out;
    float* out_us     = out + (size_t)(TH + 1) * NX;
    float* out_costs  = out_us + (size_t)TH * NU;

    k_setup<<<96, NT>>>(F, C, c);
    k_backward<<<GB, NT>>>(F, f, C, c);
    k_initP<<<64, 256>>>();
    k_sq<<<65, 256>>>(0);   // M^2
    k_sq<<<65, 256>>>(1);   // M^4
    k_sq<<<65, 256>>>(0);   // M^8
    k_sq<<<65, 256>>>(1);   // M^16  (result in g_P[0], g_pb[0])
    k_heads<<<1, 256>>>(x0, out_states);
    k_fill<<<128, 256>>>(out_states);
    k_epilogue<<<(TH + 4) / 4, 192>>>(C, c, out_states, out_us, out_costs);
}

// round 9
// speedup vs baseline: 1.5220x; 1.0084x over previous
#include <cuda_runtime.h>
#include <cstdint>

#define NX 128
#define NU 64
#define ND 192
#define TH 2048
#define GB 32
#define NT 256
#define RPB 6
#define SEG 32
#define IT_SW 32   // GJ for it < IT_SW, warm Newton after

__device__ __align__(16) float g_Ft[ND * NX];
__device__ __align__(16) float g_Vb[2][NX * NX];
__device__ __align__(16) float g_vb[2][NX];
__device__ __align__(16) float g_Q[ND * ND];
__device__ __align__(16) float g_q[ND];
__device__ __align__(16) float g_invb[2][NU * NU];   // inverse ping-pong
__device__ __align__(16) float g_T[NU * NU];         // Newton temp Q_uu * X
__device__ float g_Ks[(size_t)TH * NU * NX];
__device__ float g_ks[TH * NU];
__device__ float g_Ms[(size_t)TH * NX * NX];
__device__ float g_bs[TH * NX];
__device__ __align__(16) float g_P[2][NX * NX];
__device__ __align__(16) float g_pb[2][NX];
__device__ unsigned g_delta[TH];
__device__ unsigned g_vmax[TH];
__device__ int g_niters;
__device__ unsigned g_barcnt = 0;
__device__ unsigned g_bargen = 0;

__device__ __forceinline__ void gbar() {
    __syncthreads();
    if (threadIdx.x == 0) {
        __threadfence();
        volatile unsigned* vg = &g_bargen;
        unsigned gen = *vg;
        if (atomicAdd(&g_barcnt, 1u) == (unsigned)(GB - 1)) {
            g_barcnt = 0u;
            __threadfence();
            atomicAdd(&g_bargen, 1u);
        } else {
            while (*vg == gen) {}
        }
        __threadfence();
    }
    __syncthreads();
}

__global__ void __launch_bounds__(NT) k_setup(const float* __restrict__ F,
                                              const float* __restrict__ C,
                                              const float* __restrict__ c) {
    int idx = blockIdx.x * NT + threadIdx.x;
    if (idx < ND * NX) {
        int i = idx / NX, m = idx - i * NX;
        g_Ft[i * NX + m] = F[m * ND + i];
    }
    if (idx < NX * NX) {
        int i = idx >> 7, j = idx & 127;
        g_Vb[0][idx] = C[i * ND + j];
    }
    if (idx < NX) g_vb[0][idx] = c[idx];
    if (idx < TH) { g_delta[idx] = 0u; g_vmax[idx] = 0u; }
    if (idx == 0) g_niters = TH;
}

// ---------------- backward Riccati (persistent, 32 CTAs, 3 barriers/iter) ----------------
__global__ void __launch_bounds__(NT) k_backward(const float* __restrict__ F,
                                                 const float* __restrict__ f,
                                                 const float* __restrict__ C,
                                                 const float* __restrict__ c) {
    const int b = blockIdx.x, tid = threadIdx.x;
    const int jb = b * 4;          // owned K / V' / M columns
    const int c0 = b * 2;          // owned X' / T columns

    __shared__ float ft2[2][NX];
    __shared__ float fv2[2][NX];
    __shared__ float qred[8];
    __shared__ float prA[64], prI[64], fsh[64];
    __shared__ float pivsh;
    __shared__ float rmax[8], rvmx[8];
    __shared__ float Xs[64 * 65];
    __shared__ float Ts[64 * 65];
    __shared__ float ysh[4][64], uvs[4][64];
    __shared__ float qush[64], uqs[64];
    __shared__ float Ksh[NU * 4];
    __shared__ float ksh[NU];

    for (int it = 0; it < TH; ++it) {
        const int p = it & 1;
        const bool newton = (it >= IT_SW);
        const float* V  = g_Vb[p];
        const float* v  = g_vb[p];
        float* Vn = g_Vb[p ^ 1];
        float* vn = g_vb[p ^ 1];

        // ===== phase 1: this CTA's 6 rows of Q (and q) =====
        const int i0 = b * RPB;
        for (int pr = 0; pr < RPB; pr += 2) {
            const int ri = tid >> 7;
            const int m  = tid & 127;
            const int i  = i0 + pr + ri;
            ft2[ri][m] = g_Ft[i * NX + m];
            __syncthreads();
            float a0 = 0.f, a1 = 0.f, a2 = 0.f, a3 = 0.f;
            #pragma unroll 8
            for (int k = 0; k < NX; k += 4) {
                a0 += ft2[ri][k    ] * __ldcg(&V[(k    ) * NX + m]);
                a1 += ft2[ri][k + 1] * __ldcg(&V[(k + 1) * NX + m]);
                a2 += ft2[ri][k + 2] * __ldcg(&V[(k + 2) * NX + m]);
                a3 += ft2[ri][k + 3] * __ldcg(&V[(k + 3) * NX + m]);
            }
            float fv = (a0 + a1) + (a2 + a3);
            fv2[ri][m] = fv;
            float pq = fv * f[m] + ft2[ri][m] * __ldcg(&v[m]);
            #pragma unroll
            for (int o = 16; o > 0; o >>= 1) pq += __shfl_down_sync(0xffffffffu, pq, o);
            if ((tid & 31) == 0) qred[tid >> 5] = pq;
            __syncthreads();
            if (tid < 2) {
                float s = qred[tid * 4] + qred[tid * 4 + 1] + qred[tid * 4 + 2] + qred[tid * 4 + 3];
                g_q[i0 + pr + tid] = c[i0 + pr + tid] + s;
            }
            #pragma unroll
            for (int rr = 0; rr < 2; ++rr) {
                const int irow = i0 + pr + rr;
                if (tid < ND) {
                    float b0 = 0.f, b1 = 0.f, b2 = 0.f, b3 = 0.f;
                    #pragma unroll 8
                    for (int mm = 0; mm < NX; mm += 4) {
                        b0 += fv2[rr][mm    ] * F[(mm    ) * ND + tid];
                        b1 += fv2[rr][mm + 1] * F[(mm + 1) * ND + tid];
                        b2 += fv2[rr][mm + 2] * F[(mm + 2) * ND + tid];
                        b3 += fv2[rr][mm + 3] * F[(mm + 3) * ND + tid];
                    }
                    g_Q[irow * ND + tid] = C[irow * ND + tid] + (b0 + b1) + (b2 + b3);
                }
            }
            __syncthreads();
        }
        gbar();   // barrier 1: Q ready

        // ===== phase 2: inverse =====
        if (!newton) {
            // full Gauss-Jordan on CTA0 -> g_invb[p^1]
            if (b == 0) {
                const int r = tid >> 2, q4 = tid & 3;
                float ar[16], vi[16];
                #pragma unroll
                for (int jj = 0; jj < 16; ++jj) {
                    int col = q4 * 16 + jj;
                    ar[jj] = __ldcg(&g_Q[(NX + r) * ND + NX + col]);
                    vi[jj] = (col == r) ? 1.0f : 0.0f;
                }
                #pragma unroll
                for (int pv = 0; pv < 64; ++pv) {
                    const int ps = pv >> 4, pj = pv & 15;
                    if (r == pv && q4 == ps) pivsh = 1.0f / ar[pj];
                    __syncthreads();
                    const float pvv = pivsh;
                    if (r == pv) {
                        #pragma unroll
                        for (int jj = 0; jj < 16; ++jj) {
                            ar[jj] *= pvv; vi[jj] *= pvv;
                            prA[q4 * 16 + jj] = ar[jj];
                            prI[q4 * 16 + jj] = vi[jj];
                        }
                    }
                    if (q4 == ps) fsh[r] = ar[pj];
                    __syncthreads();
                    if (r != pv) {
                        const float fr = fsh[r];
                        #pragma unroll
                        for (int jj = 0; jj < 16; ++jj) {
                            ar[jj] -= fr * prA[q4 * 16 + jj];
                            vi[jj] -= fr * prI[q4 * 16 + jj];
                        }
                    }
                    __syncthreads();
                }
                #pragma unroll
                for (int jj = 0; jj < 16; ++jj) g_invb[p ^ 1][r * 64 + q4 * 16 + jj] = vi[jj];
            }
        } else {
            // T = Q_uu * X_old : this CTA's 2 columns
            if (tid < 128) {
                const int r = tid & 63, ci = tid >> 6;
                const int cc = c0 + ci;
                float a0 = 0.f, a1 = 0.f;
                #pragma unroll 8
                for (int m = 0; m < NU; m += 2) {
                    a0 += __ldcg(&g_Q[(NX + r) * ND + NX + m    ]) * __ldcg(&g_invb[p][(m    ) * NU + cc]);
                    a1 += __ldcg(&g_Q[(NX + r) * ND + NX + m + 1]) * __ldcg(&g_invb[p][(m + 1) * NU + cc]);
                }
                g_T[r * NU + cc] = a0 + a1;
            }
        }
        gbar();   // barrier 2: inverse / T ready

        // ===== fused phase: K, X', k, V', v', M, b, delta =====
        {
            const float* Xsrc = newton ? g_invb[p] : g_invb[p ^ 1];
            for (int o = tid; o < NU * NU; o += NT) {
                int r = o >> 6, cc = o & 63;
                Xs[r * 65 + cc] = __ldcg(&Xsrc[o]);
            }
            if (newton) {
                for (int o = tid; o < NU * NU; o += NT) {
                    int r = o >> 6, cc = o & 63;
                    Ts[r * 65 + cc] = __ldcg(&g_T[o]);
                }
            }
            {
                int jj = tid >> 6, m = tid & 63;
                ysh[jj][m] = __ldcg(&g_Q[(NX + m) * ND + jb + jj]);
            }
            if (tid < 64) qush[tid] = __ldcg(&g_q[NX + tid]);
            __syncthreads();

            // uvs = (2I - T)^T-applied: uv_j = 2 y_j - T y_j  (or y_j for GJ)
            {
                int jj = tid >> 6, m = tid & 63;
                if (newton) {
                    float s0 = 0.f, s1 = 0.f;
                    #pragma unroll 8
                    for (int r = 0; r < NU; r += 2) {
                        s0 += Ts[m * 65 + r    ] * ysh[jj][r    ];
                        s1 += Ts[m * 65 + r + 1] * ysh[jj][r + 1];
                    }
                    uvs[jj][m] = 2.0f * ysh[jj][m] - (s0 + s1);
                } else {
                    uvs[jj][m] = ysh[jj][m];
                }
            }
            if (b == 0 && tid < 64) {
                if (newton) {
                    float s = 0.f;
                    #pragma unroll 8
                    for (int r = 0; r < NU; ++r) s += Ts[tid * 65 + r] * qush[r];
                    uqs[tid] = 2.0f * qush[tid] - s;
                } else {
                    uqs[tid] = qush[tid];
                }
            }
            __syncthreads();

            // K[u][j] = -sum_m X[u][m] * uv_j[m]   (this CTA's 4 columns)
            {
                const int u = tid >> 2, jj = tid & 3;
                float s0 = 0.f, s1 = 0.f;
                #pragma unroll 8
                for (int m = 0; m < NU; m += 2) {
                    s0 += Xs[u * 65 + m    ] * uvs[jj][m    ];
                    s1 += Xs[u * 65 + m + 1] * uvs[jj][m + 1];
                }
                float kv = -(s0 + s1);
                Ksh[u * 4 + jj] = kv;
                g_Ks[(size_t)it * (NU * NX) + u * NX + jb + jj] = kv;
            }
            // X' = 2X - X*T : own 2 columns -> other buffer (next iter's warm start)
            if (newton && tid < 128) {
                const int r = tid & 63, ci = tid >> 6;
                const int cc = c0 + ci;
                float s0 = 0.f, s1 = 0.f;
                #pragma unroll 8
                for (int m = 0; m < NU; m += 2) {
                    s0 += Xs[r * 65 + m    ] * Ts[(m    ) * 65 + cc];
                    s1 += Xs[r * 65 + m + 1] * Ts[(m + 1) * 65 + cc];
                }
                g_invb[p ^ 1][r * NU + cc] = 2.0f * Xs[r * 65 + cc] - (s0 + s1);
            }
            // k = -X' q_u  (CTA0)
            if (b == 0 && tid < 64) {
                float s = 0.f;
                #pragma unroll 8
                for (int m = 0; m < NU; ++m) s += Xs[tid * 65 + m] * uqs[m];
                float kv = -s;
                ksh[tid] = kv;
                g_ks[it * NU + tid] = kv;
            }
            __syncthreads();

            // V', M for own 4 columns; delta
            float dmax = 0.f, vmx = 0.f;
            #pragma unroll
            for (int h = 0; h < 2; ++h) {
                const int o = tid + h * NT;     // 0..511
                const int i = o >> 2, jj = o & 3, j = jb + jj;
                float a0 = 0.f, a1 = 0.f, m0 = 0.f, m1 = 0.f;
                #pragma unroll 8
                for (int u = 0; u < NU; u += 2) {
                    float k0 = Ksh[(u    ) * 4 + jj];
                    float k1 = Ksh[(u + 1) * 4 + jj];
                    a0 += __ldcg(&g_Q[i * ND + NX + u    ]) * k0;
                    a1 += __ldcg(&g_Q[i * ND + NX + u + 1]) * k1;
                    m0 += F[i * ND + NX + u    ] * k0;
                    m1 += F[i * ND + NX + u + 1] * k1;
                }
                float vnew = __ldcg(&g_Q[i * ND + j]) + (a0 + a1);
                Vn[i * NX + j] = vnew;
                dmax = fmaxf(dmax, fabsf(vnew - __ldcg(&V[i * NX + j])));
                vmx  = fmaxf(vmx, fabsf(vnew));
                g_Ms[(size_t)it * (NX * NX) + i * NX + j] = F[i * ND + j] + (m0 + m1);
            }
            if (b == 0 && tid < NX) {
                float s = 0.f, sb = 0.f;
                #pragma unroll 8
                for (int u = 0; u < NU; ++u) {
                    float kk = ksh[u];
                    s  += __ldcg(&g_Q[tid * ND + NX + u]) * kk;
                    sb += F[tid * ND + NX + u] * kk;
                }
                vn[tid] = __ldcg(&g_q[tid]) + s;
                g_bs[it * NX + tid] = f[tid] + sb;
            }
            #pragma unroll
            for (int o = 16; o > 0; o >>= 1) {
                dmax = fmaxf(dmax, __shfl_down_sync(0xffffffffu, dmax, o));
                vmx  = fmaxf(vmx,  __shfl_down_sync(0xffffffffu, vmx, o));
            }
            if ((tid & 31) == 0) { rmax[tid >> 5] = dmax; rvmx[tid >> 5] = vmx; }
            __syncthreads();
            if (tid == 0) {
                float d = rmax[0], vv = rvmx[0];
                #pragma unroll
                for (int w = 1; w < 8; ++w) { d = fmaxf(d, rmax[w]); vv = fmaxf(vv, rvmx[w]); }
                atomicMax(&g_delta[it], __float_as_uint(d));
                atomicMax(&g_vmax[it], __float_as_uint(vv));
            }
        }
        gbar();   // barrier 3: end of iteration

        {
            float dd = __uint_as_float(__ldcg(&g_delta[it]));
            float vv = __uint_as_float(__ldcg(&g_vmax[it]));
            if (dd <= 1e-6f * vv) {
                if (b == 0 && tid == 0) g_niters = it + 1;
                break;
            }
        }
    }
}

// ---------------- init (M_conv, b_conv) into power buffer 0 ----------------
__global__ void __launch_bounds__(256) k_initP() {
    const int ni = g_niters;
    int o = blockIdx.x * 256 + threadIdx.x;
    if (o < NX * NX) g_P[0][o] = g_Ms[(size_t)(ni - 1) * (NX * NX) + o];
    if (o < NX) g_pb[0][o] = g_bs[(ni - 1) * NX + o];
}

// ---------------- tiled affine squaring: (M,b) -> (M*M, M*b + b) ----------------
__global__ void __launch_bounds__(256) k_sq(int p) {
    const float* __restrict__ Ms = g_P[p];
    const float* __restrict__ bs = g_pb[p];
    float* Md = g_P[p ^ 1];
    float* bd = g_pb[p ^ 1];
    const int tid = threadIdx.x;

    if (blockIdx.x == 16) {
        if (tid < NX) {
            float s0 = 0.f, s1 = 0.f;
            #pragma unroll 8
            for (int k = 0; k < NX; k += 2) {
                s0 += Ms[tid * NX + k    ] * bs[k    ];
                s1 += Ms[tid * NX + k + 1] * bs[k + 1];
            }
            bd[tid] = (s0 + s1) + bs[tid];
        }
        return;
    }

    __shared__ float As[32][33], Bs[32][33];
    const int tr = blockIdx.x >> 2, tc = blockIdx.x & 3;
    const int r  = tid >> 3;
    const int c4 = (tid & 7) * 4;
    float acc0 = 0.f, acc1 = 0.f, acc2 = 0.f, acc3 = 0.f;

    for (int kb = 0; kb < 4; ++kb) {
        #pragma unroll
        for (int l = tid; l < 1024; l += 256) {
            int lr = l >> 5, lc = l & 31;
            As[lr][lc] = Ms[(tr * 32 + lr) * NX + kb * 32 + lc];
            Bs[lr][lc] = Ms[(kb * 32 + lr) * NX + tc * 32 + lc];
        }
        __syncthreads();
        #pragma unroll
        for (int k = 0; k < 32; ++k) {
            float av = As[r][k];
            acc0 += av * Bs[k][c4    ];
            acc1 += av * Bs[k][c4 + 1];
            acc2 += av * Bs[k][c4 + 2];
            acc3 += av * Bs[k][c4 + 3];
        }
        __syncthreads();
    }
    float* dst = Md + (size_t)(tr * 32 + r) * NX + tc * 32 + c4;
    dst[0] = acc0; dst[1] = acc1; dst[2] = acc2; dst[3] = acc3;
}

// ---------------- segment heads (M^32 chain) + time-varying tail ----------------
__global__ void __launch_bounds__(256) k_heads(const float* __restrict__ x0,
                                               float* __restrict__ out_states) {
    const int tid = threadIdx.x;
    const int row = tid & 127, half = tid >> 7;
    const int ni = g_niters;
    const int tconv = TH - ni;
    const int NS = (tconv + 1) / SEG;
    __shared__ float xs[NX];
    __shared__ float ps[256];

    float mreg[64];
    {
        const float* Mc = g_P[1] + row * NX + half * 64;   // M^32 after 5 squarings
        #pragma unroll
        for (int j = 0; j < 64; j += 4) {
            float4 t4 = *(const float4*)(Mc + j);
            mreg[j] = t4.x; mreg[j + 1] = t4.y; mreg[j + 2] = t4.z; mreg[j + 3] = t4.w;
        }
    }
    float breg = g_pb[1][row];

    if (tid < NX) { xs[tid] = x0[tid]; out_states[tid] = x0[tid]; }
    __syncthreads();

    for (int s = 1; s <= NS; ++s) {
        float a0 = 0.f, a1 = 0.f, a2 = 0.f, a3 = 0.f;
        #pragma unroll
        for (int j = 0; j < 64; j += 4) {
            a0 += mreg[j    ] * xs[half * 64 + j    ];
            a1 += mreg[j + 1] * xs[half * 64 + j + 1];
            a2 += mreg[j + 2] * xs[half * 64 + j + 2];
            a3 += mreg[j + 3] * xs[half * 64 + j + 3];
        }
        ps[tid] = (a0 + a1) + (a2 + a3);
        __syncthreads();
        if (half == 0) {
            float xn = ps[row] + ps[128 + row] + breg;
            xs[row] = xn;
            out_states[(size_t)s * SEG * NX + row] = xn;
        }
        __syncthreads();
    }

    {
        const float* Mc = g_Ms + (size_t)(ni - 1) * (NX * NX) + row * NX + half * 64;
        #pragma unroll
        for (int j = 0; j < 64; j += 4) {
            float4 t4 = *(const float4*)(Mc + j);
            mreg[j] = t4.x; mreg[j + 1] = t4.y; mreg[j + 2] = t4.z; mreg[j + 3] = t4.w;
        }
        breg = g_bs[(ni - 1) * NX + row];
    }
    for (int t = NS * SEG; t < TH; ++t) {
        if (t > tconv) {
            const int r = TH - 1 - t;
            const float* Mr = g_Ms + (size_t)r * (NX * NX) + row * NX + half * 64;
            #pragma unroll
            for (int j = 0; j < 64; j += 4) {
                float4 t4 = *(const float4*)(Mr + j);
                mreg[j] = t4.x; mreg[j + 1] = t4.y; mreg[j + 2] = t4.z; mreg[j + 3] = t4.w;
            }
            breg = g_bs[r * NX + row];
        }
        float a0 = 0.f, a1 = 0.f, a2 = 0.f, a3 = 0.f;
        #pragma unroll
        for (int j = 0; j < 64; j += 4) {
            a0 += mreg[j    ] * xs[half * 64 + j    ];
            a1 += mreg[j + 1] * xs[half * 64 + j + 1];
            a2 += mreg[j + 2] * xs[half * 64 + j + 2];
            a3 += mreg[j + 3] * xs[half * 64 + j + 3];
        }
        ps[tid] = (a0 + a1) + (a2 + a3);
        __syncthreads();
        if (half == 0) {
            float xn = ps[row] + ps[128 + row] + breg;
            xs[row] = xn;
            out_states[(size_t)(t + 1) * NX + row] = xn;
        }
        __syncthreads();
    }
}

// ---------------- parallel segment fill (31 interior states per segment) ----------------
__global__ void __launch_bounds__(256) k_fill(float* __restrict__ out_states) {
    const int s = blockIdx.x;
    const int tid = threadIdx.x;
    const int row = tid & 127, half = tid >> 7;
    const int ni = g_niters;
    const int tconv = TH - ni;
    const int NS = (tconv + 1) / SEG;
    if (s >= NS) return;
    __shared__ float xs[NX];
    __shared__ float ps[256];

    float mreg[64];
    {
        const float* Mc = g_Ms + (size_t)(ni - 1) * (NX * NX) + row * NX + half * 64;
        #pragma unroll
        for (int j = 0; j < 64; j += 4) {
            float4 t4 = *(const float4*)(Mc + j);
            mreg[j] = t4.x; mreg[j + 1] = t4.y; mreg[j + 2] = t4.z; mreg[j + 3] = t4.w;
        }
    }
    float breg = g_bs[(ni - 1) * NX + row];

    if (tid < NX) xs[tid] = out_states[(size_t)s * SEG * NX + tid];
    __syncthreads();

    #pragma unroll 1
    for (int j2 = 1; j2 < SEG; ++j2) {
        float a0 = 0.f, a1 = 0.f, a2 = 0.f, a3 = 0.f;
        #pragma unroll
        for (int j = 0; j < 64; j += 4) {
            a0 += mreg[j    ] * xs[half * 64 + j    ];
            a1 += mreg[j + 1] * xs[half * 64 + j + 1];
            a2 += mreg[j + 2] * xs[half * 64 + j + 2];
            a3 += mreg[j + 3] * xs[half * 64 + j + 3];
        }
        ps[tid] = (a0 + a1) + (a2 + a3);
        __syncthreads();
        if (half == 0) {
            float xn = ps[row] + ps[128 + row] + breg;
            xs[row] = xn;
            out_states[(size_t)(s * SEG + j2) * NX + row] = xn;
        }
        __syncthreads();
    }
}

// ---------------- epilogue: 4 timesteps per block ----------------
__global__ void __launch_bounds__(192) k_epilogue(const float* __restrict__ C,
                                                  const float* __restrict__ c,
                                                  const float* __restrict__ states,
                                                  float* __restrict__ us,
                                                  float* __restrict__ costs) {
    const int t0 = blockIdx.x * 4, tid = threadIdx.x;
    const int ni = g_niters;
    __shared__ float zs[4][ND];
    __shared__ float red[192];

    #pragma unroll
    for (int k = 0; k < 4; ++k) {
        int t = t0 + k;
        if (tid < NX) zs[k][tid] = (t <= TH) ? states[(size_t)t * NX + tid] : 0.0f;
        else zs[k][tid] = 0.0f;
    }
    __syncthreads();

    if (tid < NU) {
        #pragma unroll
        for (int k = 0; k < 4; ++k) {
            int t = t0 + k;
            if (t < TH) {
                int r = TH - 1 - t; if (r > ni - 1) r = ni - 1;
                const float* Kr = g_Ks + (size_t)r * (NU * NX) + tid * NX;
                float a0 = 0.f, a1 = 0.f, a2 = 0.f, a3 = 0.f;
                #pragma unroll 8
                for (int j = 0; j < NX; j += 4) {
                    a0 += Kr[j    ] * zs[k][j    ];
                    a1 += Kr[j + 1] * zs[k][j + 1];
                    a2 += Kr[j + 2] * zs[k][j + 2];
                    a3 += Kr[j + 3] * zs[k][j + 3];
                }
                float u = g_ks[r * NU + tid] + (a0 + a1) + (a2 + a3);
                zs[k][NX + tid] = u;
                us[(size_t)t * NU + tid] = u;
            }
        }
    }
    __syncthreads();

    float cz0 = 0.f, cz1 = 0.f, cz2 = 0.f, cz3 = 0.f;
    #pragma unroll 4
    for (int i = 0; i < ND; ++i) {
        float Cv = C[i * ND + tid];
        cz0 += zs[0][i] * Cv;
        cz1 += zs[1][i] * Cv;
        cz2 += zs[2][i] * Cv;
        cz3 += zs[3][i] * Cv;
    }
    const float cv = c[tid];
    float val[4];
    val[0] = zs[0][tid] * (0.5f * cz0 + cv);
    val[1] = zs[1][tid] * (0.5f * cz1 + cv);
    val[2] = zs[2][tid] * (0.5f * cz2 + cv);
    val[3] = zs[3][tid] * (0.5f * cz3 + cv);

    #pragma unroll
    for (int k = 0; k < 4; ++k) {
        __syncthreads();
        red[tid] = val[k];
        __syncthreads();
        #pragma unroll
        for (int s = 96; s >= 6; s >>= 1) {
            if (tid < s) red[tid] += red[tid + s];
            __syncthreads();
        }
        int t = t0 + k;
        if (tid == 0 && t <= TH)
            costs[t] = red[0] + red[1] + red[2] + red[3] + red[4] + red[5];
    }
}

// ---------------- launch ----------------
extern "C" void kernel_launch(void* const* d_in, const int* in_sizes, int n_in,
                              void* d_out, int out_size) {
    const float* F  = (const float*)d_in[0];
    const float* f  = (const float*)d_in[1];
    const float* C  = (const float*)d_in[2];
    const float* c  = (const float*)d_in[3];
    const float* x0 = (const float*)d_in[4];
    (void)in_sizes; (void)n_in; (void)out_size;

    float* out        = (float*)d_out;
    float* out_states = out;
    float* out_us     = out + (size_t)(TH + 1) * NX;
    float* out_costs  = out_us + (size_t)TH * NU;

    k_setup<<<96, NT>>>(F, C, c);
    k_backward<<<GB, NT>>>(F, f, C, c);
    k_initP<<<64, 256>>>();
    k_sq<<<17, 256>>>(0);   // M^2
    k_sq<<<17, 256>>>(1);   // M^4
    k_sq<<<17, 256>>>(0);   // M^8
    k_sq<<<17, 256>>>(1);   // M^16
    k_sq<<<17, 256>>>(0);   // M^32 -> g_P[1]
    k_heads<<<1, 256>>>(x0, out_states);
    k_fill<<<64, 256>>>(out_states);
    k_epilogue<<<(TH + 4) / 4, 192>>>(C, c, out_states, out_us, out_costs);
}

// round 11
// speedup vs baseline: 1.5306x; 1.0057x over previous
#include <cuda_runtime.h>
#include <cstdint>

#define NX 128
#define NU 64
#define ND 192
#define TH 2048
#define GB 32
#define NT 256
#define RPB 6
#define SEG 32
#define IT_SW 32
#define PB 17          // power-kernel blocks
#define SMEM_BK (NX * NX * 4)   // 64KB dynamic: staged V

__device__ __align__(16) float g_Ft[ND * NX];
__device__ __align__(16) float g_Vb[2][NX * NX];
__device__ __align__(16) float g_vb[2][NX];
__device__ __align__(16) float g_Q[ND * ND];
__device__ __align__(16) float g_q[ND];
__device__ __align__(16) float g_invb[2][NU * NU];
__device__ __align__(16) float g_T[NU * NU];
__device__ float g_Ks[(size_t)TH * NU * NX];
__device__ float g_ks[TH * NU];
__device__ float g_Ms[(size_t)TH * NX * NX];
__device__ float g_bs[TH * NX];
__device__ __align__(16) float g_P[2][NX * NX];
__device__ __align__(16) float g_pb[2][NX];
__device__ unsigned g_delta[TH];
__device__ unsigned g_vmax[TH];
__device__ int g_niters;
__device__ unsigned g_barcnt = 0;
__device__ unsigned g_bargen = 0;
__device__ unsigned g_barcnt2 = 0;
__device__ unsigned g_bargen2 = 0;

__device__ __forceinline__ void gbar_n(unsigned* cnt, unsigned* gen_p, unsigned nb) {
    __syncthreads();
    if (threadIdx.x == 0) {
        __threadfence();
        volatile unsigned* vg = gen_p;
        unsigned gen = *vg;
        if (atomicAdd(cnt, 1u) == nb - 1) {
            *cnt = 0u;
            __threadfence();
            atomicAdd(gen_p, 1u);
        } else {
            while (*vg == gen) {}
        }
        __threadfence();
    }
    __syncthreads();
}
__device__ __forceinline__ void gbar() { gbar_n(&g_barcnt, &g_bargen, GB); }

__global__ void __launch_bounds__(NT) k_setup(const float* __restrict__ F,
                                              const float* __restrict__ C,
                                              const float* __restrict__ c) {
    int idx = blockIdx.x * NT + threadIdx.x;
    if (idx < ND * NX) {
        int i = idx / NX, m = idx - i * NX;
        g_Ft[i * NX + m] = F[m * ND + i];
    }
    if (idx < NX * NX) {
        int i = idx >> 7, j = idx & 127;
        g_Vb[0][idx] = C[i * ND + j];
    }
    if (idx < NX) g_vb[0][idx] = c[idx];
    if (idx < TH) { g_delta[idx] = 0u; g_vmax[idx] = 0u; }
    if (idx == 0) g_niters = TH;
}

// ---------------- backward Riccati (persistent, 32 CTAs) ----------------
__global__ void __launch_bounds__(NT) k_backward(const float* __restrict__ F,
                                                 const float* __restrict__ f,
                                                 const float* __restrict__ C,
                                                 const float* __restrict__ c) {
    const int b = blockIdx.x, tid = threadIdx.x;
    const int jb = b * 4;
    const int c0 = b * 2;
    extern __shared__ float sVs[];           // 128x128 staged V

    __shared__ float ft2[2][NX];
    __shared__ float fv2[2][NX];
    __shared__ float qred[8];
    __shared__ float prA[64], prI[64], fsh[64];
    __shared__ float pivsh;
    __shared__ float rmax[8], rvmx[8];
    __shared__ float Xs[64 * 65];
    __shared__ float Ts[64 * 65];
    __shared__ float ysh[4][64], uvs[4][64];
    __shared__ float qush[64], uqs[64];
    __shared__ float Ksh[NU * 4];
    __shared__ float ksh[NU];

    for (int it = 0; it < TH; ++it) {
        const int p = it & 1;
        const bool newton = (it >= IT_SW);
        const float* V  = g_Vb[p];
        const float* v  = g_vb[p];
        float* Vn = g_Vb[p ^ 1];
        float* vn = g_vb[p ^ 1];

        // ===== phase 1: stage V in smem, build this CTA's 6 rows of Q (and q) =====
        {
            float4* Vs4 = (float4*)sVs;
            const float4* Vsrc = (const float4*)V;
            #pragma unroll
            for (int o = tid; o < (NX * NX) / 4; o += NT) Vs4[o] = __ldcg(Vsrc + o);
        }
        __syncthreads();
        const int i0 = b * RPB;
        for (int pr = 0; pr < RPB; pr += 2) {
            const int ri = tid >> 7;
            const int m  = tid & 127;
            const int i  = i0 + pr + ri;
            ft2[ri][m] = g_Ft[i * NX + m];
            __syncthreads();
            float a0 = 0.f, a1 = 0.f, a2 = 0.f, a3 = 0.f;
            const float4* ftv = (const float4*)ft2[ri];
            #pragma unroll 8
            for (int k = 0; k < NX; k += 4) {
                float4 f4 = ftv[k >> 2];
                a0 += f4.x * sVs[(k    ) * NX + m];
                a1 += f4.y * sVs[(k + 1) * NX + m];
                a2 += f4.z * sVs[(k + 2) * NX + m];
                a3 += f4.w * sVs[(k + 3) * NX + m];
            }
            float fv = (a0 + a1) + (a2 + a3);
            fv2[ri][m] = fv;
            float pq = fv * f[m] + ft2[ri][m] * __ldcg(&v[m]);
            #pragma unroll
            for (int o = 16; o > 0; o >>= 1) pq += __shfl_down_sync(0xffffffffu, pq, o);
            if ((tid & 31) == 0) qred[tid >> 5] = pq;
            __syncthreads();
            if (tid < 2) {
                float s = qred[tid * 4] + qred[tid * 4 + 1] + qred[tid * 4 + 2] + qred[tid * 4 + 3];
                g_q[i0 + pr + tid] = c[i0 + pr + tid] + s;
            }
            #pragma unroll
            for (int rr = 0; rr < 2; ++rr) {
                const int irow = i0 + pr + rr;
                if (tid < ND) {
                    float b0 = 0.f, b1 = 0.f, b2 = 0.f, b3 = 0.f;
                    const float4* fvv = (const float4*)fv2[rr];
                    #pragma unroll 8
                    for (int mm = 0; mm < NX; mm += 4) {
                        float4 f4 = fvv[mm >> 2];
                        b0 += f4.x * F[(mm    ) * ND + tid];
                        b1 += f4.y * F[(mm + 1) * ND + tid];
                        b2 += f4.z * F[(mm + 2) * ND + tid];
                        b3 += f4.w * F[(mm + 3) * ND + tid];
                    }
                    g_Q[irow * ND + tid] = C[irow * ND + tid] + (b0 + b1) + (b2 + b3);
                }
            }
            __syncthreads();
        }
        gbar();   // barrier 1: Q ready

        // ===== phase 2: inverse =====
        if (!newton) {
            if (b == 0) {
                const int r = tid >> 2, q4 = tid & 3;
                float ar[16], vi[16];
                #pragma unroll
                for (int jj = 0; jj < 16; ++jj) {
                    int col = q4 * 16 + jj;
                    ar[jj] = __ldcg(&g_Q[(NX + r) * ND + NX + col]);
                    vi[jj] = (col == r) ? 1.0f : 0.0f;
                }
                #pragma unroll
                for (int pv = 0; pv < 64; ++pv) {
                    const int ps = pv >> 4, pj = pv & 15;
                    if (r == pv && q4 == ps) pivsh = 1.0f / ar[pj];
                    __syncthreads();
                    const float pvv = pivsh;
                    if (r == pv) {
                        #pragma unroll
                        for (int jj = 0; jj < 16; ++jj) {
                            ar[jj] *= pvv; vi[jj] *= pvv;
                            prA[q4 * 16 + jj] = ar[jj];
                            prI[q4 * 16 + jj] = vi[jj];
                        }
                    }
                    if (q4 == ps) fsh[r] = ar[pj];
                    __syncthreads();
                    if (r != pv) {
                        const float fr = fsh[r];
                        #pragma unroll
                        for (int jj = 0; jj < 16; ++jj) {
                            ar[jj] -= fr * prA[q4 * 16 + jj];
                            vi[jj] -= fr * prI[q4 * 16 + jj];
                        }
                    }
                    __syncthreads();
                }
                #pragma unroll
                for (int jj = 0; jj < 16; ++jj) g_invb[p ^ 1][r * 64 + q4 * 16 + jj] = vi[jj];
            }
        } else {
            if (tid < 128) {
                const int r = tid & 63, ci = tid >> 6;
                const int cc = c0 + ci;
                float a0 = 0.f, a1 = 0.f;
                #pragma unroll 8
                for (int m = 0; m < NU; m += 2) {
                    a0 += __ldcg(&g_Q[(NX + r) * ND + NX + m    ]) * __ldcg(&g_invb[p][(m    ) * NU + cc]);
                    a1 += __ldcg(&g_Q[(NX + r) * ND + NX + m + 1]) * __ldcg(&g_invb[p][(m + 1) * NU + cc]);
                }
                g_T[r * NU + cc] = a0 + a1;
            }
        }
        gbar();   // barrier 2: inverse / T ready

        // ===== fused phase: K, X', k, V', v', M, b, delta =====
        {
            const float* Xsrc = newton ? g_invb[p] : g_invb[p ^ 1];
            for (int o = tid; o < NU * NU; o += NT) {
                int r = o >> 6, cc = o & 63;
                Xs[r * 65 + cc] = __ldcg(&Xsrc[o]);
            }
            if (newton) {
                for (int o = tid; o < NU * NU; o += NT) {
                    int r = o >> 6, cc = o & 63;
                    Ts[r * 65 + cc] = __ldcg(&g_T[o]);
                }
            }
            {
                int jj = tid >> 6, m = tid & 63;
                ysh[jj][m] = __ldcg(&g_Q[(NX + m) * ND + jb + jj]);
            }
            if (tid < 64) qush[tid] = __ldcg(&g_q[NX + tid]);
            __syncthreads();

            {
                int jj = tid >> 6, m = tid & 63;
                if (newton) {
                    float s0 = 0.f, s1 = 0.f;
                    #pragma unroll 8
                    for (int r = 0; r < NU; r += 2) {
                        s0 += Ts[m * 65 + r    ] * ysh[jj][r    ];
                        s1 += Ts[m * 65 + r + 1] * ysh[jj][r + 1];
                    }
                    uvs[jj][m] = 2.0f * ysh[jj][m] - (s0 + s1);
                } else {
                    uvs[jj][m] = ysh[jj][m];
                }
            }
            if (b == 0 && tid < 64) {
                if (newton) {
                    float s = 0.f;
                    #pragma unroll 8
                    for (int r = 0; r < NU; ++r) s += Ts[tid * 65 + r] * qush[r];
                    uqs[tid] = 2.0f * qush[tid] - s;
                } else {
                    uqs[tid] = qush[tid];
                }
            }
            __syncthreads();

            {
                const int u = tid >> 2, jj = tid & 3;
                float s0 = 0.f, s1 = 0.f;
                #pragma unroll 8
                for (int m = 0; m < NU; m += 2) {
                    s0 += Xs[u * 65 + m    ] * uvs[jj][m    ];
                    s1 += Xs[u * 65 + m + 1] * uvs[jj][m + 1];
                }
                float kv = -(s0 + s1);
                Ksh[u * 4 + jj] = kv;
                g_Ks[(size_t)it * (NU * NX) + u * NX + jb + jj] = kv;
            }
            if (newton && tid < 128) {
                const int r = tid & 63, ci = tid >> 6;
                const int cc = c0 + ci;
                float s0 = 0.f, s1 = 0.f;
                #pragma unroll 8
                for (int m = 0; m < NU; m += 2) {
                    s0 += Xs[r * 65 + m    ] * Ts[(m    ) * 65 + cc];
                    s1 += Xs[r * 65 + m + 1] * Ts[(m + 1) * 65 + cc];
                }
                g_invb[p ^ 1][r * NU + cc] = 2.0f * Xs[r * 65 + cc] - (s0 + s1);
            }
            if (b == 0 && tid < 64) {
                float s = 0.f;
                #pragma unroll 8
                for (int m = 0; m < NU; ++m) s += Xs[tid * 65 + m] * uqs[m];
                float kv = -s;
                ksh[tid] = kv;
                g_ks[it * NU + tid] = kv;
            }
            __syncthreads();

            float dmax = 0.f, vmx = 0.f;
            #pragma unroll
            for (int h = 0; h < 2; ++h) {
                const int o = tid + h * NT;
                const int i = o >> 2, jj = o & 3, j = jb + jj;
                float a0 = 0.f, a1 = 0.f, m0 = 0.f, m1 = 0.f;
                #pragma unroll 8
                for (int u = 0; u < NU; u += 2) {
                    float k0 = Ksh[(u    ) * 4 + jj];
                    float k1 = Ksh[(u + 1) * 4 + jj];
                    a0 += __ldcg(&g_Q[i * ND + NX + u    ]) * k0;
                    a1 += __ldcg(&g_Q[i * ND + NX + u + 1]) * k1;
                    m0 += F[i * ND + NX + u    ] * k0;
                    m1 += F[i * ND + NX + u + 1] * k1;
                }
                float vnew = __ldcg(&g_Q[i * ND + j]) + (a0 + a1);
                Vn[i * NX + j] = vnew;
                dmax = fmaxf(dmax, fabsf(vnew - __ldcg(&V[i * NX + j])));
                vmx  = fmaxf(vmx, fabsf(vnew));
                g_Ms[(size_t)it * (NX * NX) + i * NX + j] = F[i * ND + j] + (m0 + m1);
            }
            if (b == 0 && tid < NX) {
                float s = 0.f, sb = 0.f;
                #pragma unroll 8
                for (int u = 0; u < NU; ++u) {
                    float kk = ksh[u];
                    s  += __ldcg(&g_Q[tid * ND + NX + u]) * kk;
                    sb += F[tid * ND + NX + u] * kk;
                }
                vn[tid] = __ldcg(&g_q[tid]) + s;
                g_bs[it * NX + tid] = f[tid] + sb;
            }
            #pragma unroll
            for (int o = 16; o > 0; o >>= 1) {
                dmax = fmaxf(dmax, __shfl_down_sync(0xffffffffu, dmax, o));
                vmx  = fmaxf(vmx,  __shfl_down_sync(0xffffffffu, vmx, o));
            }
            if ((tid & 31) == 0) { rmax[tid >> 5] = dmax; rvmx[tid >> 5] = vmx; }
            __syncthreads();
            if (tid == 0) {
                float d = rmax[0], vv = rvmx[0];
                #pragma unroll
                for (int w = 1; w < 8; ++w) { d = fmaxf(d, rmax[w]); vv = fmaxf(vv, rvmx[w]); }
                atomicMax(&g_delta[it], __float_as_uint(d));
                atomicMax(&g_vmax[it], __float_as_uint(vv));
            }
        }
        gbar();   // barrier 3: end of iteration

        {
            float dd = __uint_as_float(__ldcg(&g_delta[it]));
            float vv = __uint_as_float(__ldcg(&g_vmax[it]));
            if (dd <= 1e-5f * vv) {
                if (b == 0 && tid == 0) g_niters = it + 1;
                break;
            }
        }
    }
}

// ---------------- persistent power kernel: copy + 5 affine squarings ----------------
__global__ void __launch_bounds__(256) k_power() {
    const int tid = threadIdx.x;
    // stage -1: copy (M_conv, b_conv) -> g_P[0]
    {
        const int ni = g_niters;
        const float* src = g_Ms + (size_t)(ni - 1) * (NX * NX);
        for (int o = blockIdx.x * 256 + tid; o < NX * NX; o += PB * 256)
            g_P[0][o] = __ldcg(&src[o]);
        if (blockIdx.x == 16 && tid < NX) g_pb[0][tid] = __ldcg(&g_bs[(ni - 1) * NX + tid]);
    }
    gbar_n(&g_barcnt2, &g_bargen2, PB);

    __shared__ float As[32][33], Bs[32][33];
    #pragma unroll 1
    for (int s = 0; s < 5; ++s) {
        const int p = s & 1;
        const float* Ms = g_P[p];
        const float* bs = g_pb[p];
        float* Md = g_P[p ^ 1];
        float* bd = g_pb[p ^ 1];

        if (blockIdx.x == 16) {
            if (tid < NX) {
                float s0 = 0.f, s1 = 0.f;
                #pragma unroll 8
                for (int k = 0; k < NX; k += 2) {
                    s0 += __ldcg(&Ms[tid * NX + k    ]) * __ldcg(&bs[k    ]);
                    s1 += __ldcg(&Ms[tid * NX + k + 1]) * __ldcg(&bs[k + 1]);
                }
                bd[tid] = (s0 + s1) + __ldcg(&bs[tid]);
            }
        } else {
            const int tr = blockIdx.x >> 2, tc = blockIdx.x & 3;
            const int r  = tid >> 3;
            const int c4 = (tid & 7) * 4;
            float acc0 = 0.f, acc1 = 0.f, acc2 = 0.f, acc3 = 0.f;
            for (int kb = 0; kb < 4; ++kb) {
                #pragma unroll
                for (int l = tid; l < 1024; l += 256) {
                    int lr = l >> 5, lc = l & 31;
                    As[lr][lc] = __ldcg(&Ms[(tr * 32 + lr) * NX + kb * 32 + lc]);
                    Bs[lr][lc] = __ldcg(&Ms[(kb * 32 + lr) * NX + tc * 32 + lc]);
                }
                __syncthreads();
                #pragma unroll
                for (int k = 0; k < 32; ++k) {
                    float av = As[r][k];
                    acc0 += av * Bs[k][c4    ];
                    acc1 += av * Bs[k][c4 + 1];
                    acc2 += av * Bs[k][c4 + 2];
                    acc3 += av * Bs[k][c4 + 3];
                }
                __syncthreads();
            }
            float* dst = Md + (size_t)(tr * 32 + r) * NX + tc * 32 + c4;
            dst[0] = acc0; dst[1] = acc1; dst[2] = acc2; dst[3] = acc3;
        }
        gbar_n(&g_barcnt2, &g_bargen2, PB);
    }
}

// ---------------- segment heads (M^32 chain) + time-varying tail ----------------
__global__ void __launch_bounds__(256) k_heads(const float* __restrict__ x0,
                                               float* __restrict__ out_states) {
    const int tid = threadIdx.x;
    const int row = tid & 127, half = tid >> 7;
    const int ni = g_niters;
    const int tconv = TH - ni;
    const int NS = (tconv + 1) / SEG;
    __shared__ float xs[NX];
    __shared__ float ps[256];

    float mreg[64];
    {
        const float* Mc = g_P[1] + row * NX + half * 64;
        #pragma unroll
        for (int j = 0; j < 64; j += 4) {
            float4 t4 = *(const float4*)(Mc + j);
            mreg[j] = t4.x; mreg[j + 1] = t4.y; mreg[j + 2] = t4.z; mreg[j + 3] = t4.w;
        }
    }
    float breg = g_pb[1][row];

    if (tid < NX) { xs[tid] = x0[tid]; out_states[tid] = x0[tid]; }
    __syncthreads();

    for (int s = 1; s <= NS; ++s) {
        float a0 = 0.f, a1 = 0.f, a2 = 0.f, a3 = 0.f;
        #pragma unroll
        for (int j = 0; j < 64; j += 4) {
            a0 += mreg[j    ] * xs[half * 64 + j    ];
            a1 += mreg[j + 1] * xs[half * 64 + j + 1];
            a2 += mreg[j + 2] * xs[half * 64 + j + 2];
            a3 += mreg[j + 3] * xs[half * 64 + j + 3];
        }
        ps[tid] = (a0 + a1) + (a2 + a3);
        __syncthreads();
        if (half == 0) {
            float xn = ps[row] + ps[128 + row] + breg;
            xs[row] = xn;
            out_states[(size_t)s * SEG * NX + row] = xn;
        }
        __syncthreads();
    }

    {
        const float* Mc = g_Ms + (size_t)(ni - 1) * (NX * NX) + row * NX + half * 64;
        #pragma unroll
        for (int j = 0; j < 64; j += 4) {
            float4 t4 = *(const float4*)(Mc + j);
            mreg[j] = t4.x; mreg[j + 1] = t4.y; mreg[j + 2] = t4.z; mreg[j + 3] = t4.w;
        }
        breg = g_bs[(ni - 1) * NX + row];
    }
    for (int t = NS * SEG; t < TH; ++t) {
        if (t > tconv) {
            const int r = TH - 1 - t;
            const float* Mr = g_Ms + (size_t)r * (NX * NX) + row * NX + half * 64;
            #pragma unroll
            for (int j = 0; j < 64; j += 4) {
                float4 t4 = *(const float4*)(Mr + j);
                mreg[j] = t4.x; mreg[j + 1] = t4.y; mreg[j + 2] = t4.z; mreg[j + 3] = t4.w;
            }
            breg = g_bs[r * NX + row];
        }
        float a0 = 0.f, a1 = 0.f, a2 = 0.f, a3 = 0.f;
        #pragma unroll
        for (int j = 0; j < 64; j += 4) {
            a0 += mreg[j    ] * xs[half * 64 + j    ];
            a1 += mreg[j + 1] * xs[half * 64 + j + 1];
            a2 += mreg[j + 2] * xs[half * 64 + j + 2];
            a3 += mreg[j + 3] * xs[half * 64 + j + 3];
        }
        ps[tid] = (a0 + a1) + (a2 + a3);
        __syncthreads();
        if (half == 0) {
            float xn = ps[row] + ps[128 + row] + breg;
            xs[row] = xn;
            out_states[(size_t)(t + 1) * NX + row] = xn;
        }
        __syncthreads();
    }
}

// ---------------- parallel segment fill ----------------
__global__ void __launch_bounds__(256) k_fill(float* __restrict__ out_states) {
    const int s = blockIdx.x;
    const int tid = threadIdx.x;
    const int row = tid & 127, half = tid >> 7;
    const int ni = g_niters;
    const int tconv = TH - ni;
    const int NS = (tconv + 1) / SEG;
    if (s >= NS) return;
    __shared__ float xs[NX];
    __shared__ float ps[256];

    float mreg[64];
    {
        const float* Mc = g_Ms + (size_t)(ni - 1) * (NX * NX) + row * NX + half * 64;
        #pragma unroll
        for (int j = 0; j < 64; j += 4) {
            float4 t4 = *(const float4*)(Mc + j);
            mreg[j] = t4.x; mreg[j + 1] = t4.y; mreg[j + 2] = t4.z; mreg[j + 3] = t4.w;
        }
    }
    float breg = g_bs[(ni - 1) * NX + row];

    if (tid < NX) xs[tid] = out_states[(size_t)s * SEG * NX + tid];
    __syncthreads();

    #pragma unroll 1
    for (int j2 = 1; j2 < SEG; ++j2) {
        float a0 = 0.f, a1 = 0.f, a2 = 0.f, a3 = 0.f;
        #pragma unroll
        for (int j = 0; j < 64; j += 4) {
            a0 += mreg[j    ] * xs[half * 64 + j    ];
            a1 += mreg[j + 1] * xs[half * 64 + j + 1];
            a2 += mreg[j + 2] * xs[half * 64 + j + 2];
            a3 += mreg[j + 3] * xs[half * 64 + j + 3];
        }
        ps[tid] = (a0 + a1) + (a2 + a3);
        __syncthreads();
        if (half == 0) {
            float xn = ps[row] + ps[128 + row] + breg;
            xs[row] = xn;
            out_states[(size_t)(s * SEG + j2) * NX + row] = xn;
        }
        __syncthreads();
    }
}

// ---------------- epilogue: 4 timesteps per block ----------------
__global__ void __launch_bounds__(192) k_epilogue(const float* __restrict__ C,
                                                  const float* __restrict__ c,
                                                  const float* __restrict__ states,
                                                  float* __restrict__ us,
                                                  float* __restrict__ costs) {
    const int t0 = blockIdx.x * 4, tid = threadIdx.x;
    const int ni = g_niters;
    __shared__ float zs[4][ND];
    __shared__ float red[192];

    #pragma unroll
    for (int k = 0; k < 4; ++k) {
        int t = t0 + k;
        if (tid < NX) zs[k][tid] = (t <= TH) ? states[(size_t)t * NX + tid] : 0.0f;
        else zs[k][tid] = 0.0f;
    }
    __syncthreads();

    if (tid < NU) {
        #pragma unroll
        for (int k = 0; k < 4; ++k) {
            int t = t0 + k;
            if (t < TH) {
                int r = TH - 1 - t; if (r > ni - 1) r = ni - 1;
                const float* Kr = g_Ks + (size_t)r * (NU * NX) + tid * NX;
                float a0 = 0.f, a1 = 0.f, a2 = 0.f, a3 = 0.f;
                #pragma unroll 8
                for (int j = 0; j < NX; j += 4) {
                    a0 += Kr[j    ] * zs[k][j    ];
                    a1 += Kr[j + 1] * zs[k][j + 1];
                    a2 += Kr[j + 2] * zs[k][j + 2];
                    a3 += Kr[j + 3] * zs[k][j + 3];
                }
                float u = g_ks[r * NU + tid] + (a0 + a1) + (a2 + a3);
                zs[k][NX + tid] = u;
                us[(size_t)t * NU + tid] = u;
            }
        }
    }
    __syncthreads();

    float cz0 = 0.f, cz1 = 0.f, cz2 = 0.f, cz3 = 0.f;
    #pragma unroll 4
    for (int i = 0; i < ND; ++i) {
        float Cv = C[i * ND + tid];
        cz0 += zs[0][i] * Cv;
        cz1 += zs[1][i] * Cv;
        cz2 += zs[2][i] * Cv;
        cz3 += zs[3][i] * Cv;
    }
    const float cv = c[tid];
    float val[4];
    val[0] = zs[0][tid] * (0.5f * cz0 + cv);
    val[1] = zs[1][tid] * (0.5f * cz1 + cv);
    val[2] = zs[2][tid] * (0.5f * cz2 + cv);
    val[3] = zs[3][tid] * (0.5f * cz3 + cv);

    #pragma unroll
    for (int k = 0; k < 4; ++k) {
        __syncthreads();
        red[tid] = val[k];
        __syncthreads();
        #pragma unroll
        for (int s = 96; s >= 6; s >>= 1) {
            if (tid < s) red[tid] += red[tid + s];
            __syncthreads();
        }
        int t = t0 + k;
        if (tid == 0 && t <= TH)
            costs[t] = red[0] + red[1] + red[2] + red[3] + red[4] + red[5];
    }
}

// ---------------- launch ----------------
extern "C" void kernel_launch(void* const* d_in, const int* in_sizes, int n_in,
                              void* d_out, int out_size) {
    const float* F  = (const float*)d_in[0];
    const float* f  = (const float*)d_in[1];
    const float* C  = (const float*)d_in[2];
    const float* c  = (const float*)d_in[3];
    const float* x0 = (const float*)d_in[4];
    (void)in_sizes; (void)n_in; (void)out_size;

    float* out        = (float*)d_out;
    float* out_states = out;
    float* out_us     = out + (size_t)(TH + 1) * NX;
    float* out_costs  = out_us + (size_t)TH * NU;

    static int smem_set = 0;
    if (!smem_set) {
        cudaFuncSetAttribute(k_backward, cudaFuncAttributeMaxDynamicSharedMemorySize, SMEM_BK);
        smem_set = 1;
    }

    k_setup<<<96, NT>>>(F, C, c);
    k_backward<<<GB, NT, SMEM_BK>>>(F, f, C, c);
    k_power<<<PB, 256>>>();
    k_heads<<<1, 256>>>(x0, out_states);
    k_fill<<<64, 256>>>(out_states);
    k_epilogue<<<(TH + 4) / 4, 192>>>(C, c, out_states, out_us, out_costs);
}

// round 12
// speedup vs baseline: 1.5371x; 1.0042x over previous
#include <cuda_runtime.h>
#include <cstdint>

#define NX 128
#define NU 64
#define ND 192
#define TH 2048
#define GB 32
#define NT 256
#define RPB 6
#define SEG 32
#define IT_SW 32
#define PB 17

// dynamic smem layout (floats)
#define OFF_QXU2 0              // 128 x 65
#define OFF_QUU  8320           // 64 x 65
#define OFF_X    12480          // 64 x 65
#define OFF_Y4   16640          // 4 x 64
#define OFF_QU   16896          // 64
#define SMEM_FLOATS 16960
#define SMEM_BK (SMEM_FLOATS * 4)   // 67840 B (>= 64KB V staging)

__device__ __align__(16) float g_Ft[ND * NX];
__device__ __align__(16) float g_Vb[2][NX * NX];
__device__ __align__(16) float g_vb[2][NX];
__device__ __align__(16) float g_Q[ND * ND];
__device__ __align__(16) float g_q[ND];
__device__ __align__(16) float g_invb[2][NU * NU];
__device__ float g_Ks[(size_t)TH * NU * NX];
__device__ float g_ks[TH * NU];
__device__ float g_Ms[(size_t)TH * NX * NX];
__device__ float g_bs[TH * NX];
__device__ __align__(16) float g_P[2][NX * NX];
__device__ __align__(16) float g_pb[2][NX];
__device__ unsigned g_delta[TH];
__device__ unsigned g_vmax[TH];
__device__ int g_niters;
__device__ unsigned g_barcnt = 0;
__device__ unsigned g_bargen = 0;
__device__ unsigned g_barcnt2 = 0;
__device__ unsigned g_bargen2 = 0;

__device__ __forceinline__ void gbar_n(unsigned* cnt, unsigned* gen_p, unsigned nb) {
    __syncthreads();
    if (threadIdx.x == 0) {
        __threadfence();
        volatile unsigned* vg = gen_p;
        unsigned gen = *vg;
        if (atomicAdd(cnt, 1u) == nb - 1) {
            *cnt = 0u;
            __threadfence();
            atomicAdd(gen_p, 1u);
        } else {
            while (*vg == gen) {}
        }
        __threadfence();
    }
    __syncthreads();
}
__device__ __forceinline__ void gbar() { gbar_n(&g_barcnt, &g_bargen, GB); }

__global__ void __launch_bounds__(NT) k_setup(const float* __restrict__ F,
                                              const float* __restrict__ C,
                                              const float* __restrict__ c) {
    int idx = blockIdx.x * NT + threadIdx.x;
    if (idx < ND * NX) {
        int i = idx / NX, m = idx - i * NX;
        g_Ft[i * NX + m] = F[m * ND + i];
    }
    if (idx < NX * NX) {
        int i = idx >> 7, j = idx & 127;
        g_Vb[0][idx] = C[i * ND + j];
    }
    if (idx < NX) g_vb[0][idx] = c[idx];
    if (idx < TH) { g_delta[idx] = 0u; g_vmax[idx] = 0u; }
    if (idx == 0) g_niters = TH;
}

// ---------------- backward Riccati (persistent, 32 CTAs, 2 barriers/iter) ----------------
__global__ void __launch_bounds__(NT) k_backward(const float* __restrict__ F,
                                                 const float* __restrict__ f,
                                                 const float* __restrict__ C,
                                                 const float* __restrict__ c) {
    const int b = blockIdx.x, tid = threadIdx.x;
    const int jb = b * 4;          // owned K / V' / M columns
    const int c0 = b * 2;          // owned X' columns
    extern __shared__ float sm[];

    __shared__ float sFu[128 * 65];          // F_u staged once (static 33KB)
    __shared__ float ft2[2][NX];
    __shared__ float fv2[2][NX];
    __shared__ float qred[8];
    __shared__ float prA[64], prI[64], fsh[64];
    __shared__ float pivsh;
    __shared__ float rmax[8], rvmx[8];
    __shared__ float Wsh[256], Zsh[256], ush[128];
    __shared__ float wqs[64], zqs[64], ksh[64];
    __shared__ float Ksh[256];

    // stage F_u once (plain loads, read-only input)
    for (int o = tid; o < 128 * 64; o += NT) {
        int i = o >> 6, u = o & 63;
        sFu[i * 65 + u] = F[i * ND + NX + u];
    }
    __syncthreads();

    for (int it = 0; it < TH; ++it) {
        const int p = it & 1;
        const bool newton = (it >= IT_SW);
        const float* V  = g_Vb[p];
        const float* v  = g_vb[p];
        float* Vn = g_Vb[p ^ 1];
        float* vn = g_vb[p ^ 1];

        // ===== phase 1: stage V, build this CTA's 6 rows of Q (and q) =====
        {
            float4* Vs4 = (float4*)sm;
            const float4* Vsrc = (const float4*)V;
            #pragma unroll
            for (int o = tid; o < (NX * NX) / 4; o += NT) Vs4[o] = __ldcg(Vsrc + o);
        }
        __syncthreads();
        const int i0 = b * RPB;
        for (int pr = 0; pr < RPB; pr += 2) {
            const int ri = tid >> 7;
            const int m  = tid & 127;
            const int i  = i0 + pr + ri;
            ft2[ri][m] = g_Ft[i * NX + m];
            __syncthreads();
            float a0 = 0.f, a1 = 0.f, a2 = 0.f, a3 = 0.f;
            const float4* ftv = (const float4*)ft2[ri];
            #pragma unroll 8
            for (int k = 0; k < NX; k += 4) {
                float4 f4 = ftv[k >> 2];
                a0 += f4.x * sm[(k    ) * NX + m];
                a1 += f4.y * sm[(k + 1) * NX + m];
                a2 += f4.z * sm[(k + 2) * NX + m];
                a3 += f4.w * sm[(k + 3) * NX + m];
            }
            float fv = (a0 + a1) + (a2 + a3);
            fv2[ri][m] = fv;
            float pq = fv * f[m] + ft2[ri][m] * __ldcg(&v[m]);
            #pragma unroll
            for (int o = 16; o > 0; o >>= 1) pq += __shfl_down_sync(0xffffffffu, pq, o);
            if ((tid & 31) == 0) qred[tid >> 5] = pq;
            __syncthreads();
            if (tid < 2) {
                float s = qred[tid * 4] + qred[tid * 4 + 1] + qred[tid * 4 + 2] + qred[tid * 4 + 3];
                g_q[i0 + pr + tid] = c[i0 + pr + tid] + s;
            }
            #pragma unroll
            for (int rr = 0; rr < 2; ++rr) {
                const int irow = i0 + pr + rr;
                if (tid < ND) {
                    float b0 = 0.f, b1 = 0.f, b2 = 0.f, b3 = 0.f;
                    const float4* fvv = (const float4*)fv2[rr];
                    #pragma unroll 8
                    for (int mm = 0; mm < NX; mm += 4) {
                        float4 f4 = fvv[mm >> 2];
                        b0 += f4.x * F[(mm    ) * ND + tid];
                        b1 += f4.y * F[(mm + 1) * ND + tid];
                        b2 += f4.z * F[(mm + 2) * ND + tid];
                        b3 += f4.w * F[(mm + 3) * ND + tid];
                    }
                    g_Q[irow * ND + tid] = C[irow * ND + tid] + (b0 + b1) + (b2 + b3);
                }
            }
            __syncthreads();
        }
        gbar();   // barrier 1: Q ready

        // grab old-V values for delta (V[p] is read-only this iter)
        float vold0, vold1;
        {
            int o0 = tid,        i_0 = o0 >> 2, j_0 = jb + (o0 & 3);
            int o1 = tid + NT,   i_1 = o1 >> 2, j_1 = jb + (o1 & 3);
            vold0 = __ldcg(&V[i_0 * NX + j_0]);
            vold1 = __ldcg(&V[i_1 * NX + j_1]);
        }

        // ===== GJ (it < IT_SW): every CTA computes its own inverse into sm[OFF_X] =====
        if (!newton) {
            const int r = tid >> 2, q4 = tid & 3;
            float ar[16], vi[16];
            #pragma unroll
            for (int jj = 0; jj < 16; ++jj) {
                int col = q4 * 16 + jj;
                ar[jj] = __ldcg(&g_Q[(NX + r) * ND + NX + col]);
                vi[jj] = (col == r) ? 1.0f : 0.0f;
            }
            #pragma unroll 1
            for (int pv = 0; pv < 64; ++pv) {
                const int ps = pv >> 4, pj = pv & 15;
                if (r == pv && q4 == ps) pivsh = 1.0f / ar[pj];
                __syncthreads();
                const float pvv = pivsh;
                if (r == pv) {
                    #pragma unroll
                    for (int jj = 0; jj < 16; ++jj) {
                        ar[jj] *= pvv; vi[jj] *= pvv;
                        prA[q4 * 16 + jj] = ar[jj];
                        prI[q4 * 16 + jj] = vi[jj];
                    }
                }
                if (q4 == ps) fsh[r] = ar[pj];
                __syncthreads();
                if (r != pv) {
                    const float fr = fsh[r];
                    #pragma unroll
                    for (int jj = 0; jj < 16; ++jj) {
                        ar[jj] -= fr * prA[q4 * 16 + jj];
                        vi[jj] -= fr * prI[q4 * 16 + jj];
                    }
                }
                __syncthreads();
            }
            #pragma unroll
            for (int jj = 0; jj < 16; ++jj) {
                sm[OFF_X + r * 65 + q4 * 16 + jj] = vi[jj];
                if (b == 0) g_invb[p ^ 1][r * 64 + q4 * 16 + jj] = vi[jj];
            }
        }

        // ===== stage cross-CTA operands into smem (bulk, high-MLP) =====
        {
            // Q_xu: 128x64 -> pitch 65
            #pragma unroll
            for (int o = tid; o < 2048; o += NT) {
                int row = o >> 4, c4 = o & 15;
                float4 q4v = __ldcg((const float4*)&g_Q[row * ND + NX + c4 * 4]);
                float* d = &sm[OFF_QXU2 + row * 65 + c4 * 4];
                d[0] = q4v.x; d[1] = q4v.y; d[2] = q4v.z; d[3] = q4v.w;
            }
            if (newton) {
                // Q_uu: 64x64 -> pitch 65
                #pragma unroll
                for (int o = tid; o < 1024; o += NT) {
                    int row = o >> 4, c4 = o & 15;
                    float4 q4v = __ldcg((const float4*)&g_Q[(NX + row) * ND + NX + c4 * 4]);
                    float* d = &sm[OFF_QUU + row * 65 + c4 * 4];
                    d[0] = q4v.x; d[1] = q4v.y; d[2] = q4v.z; d[3] = q4v.w;
                }
                // warm inverse X
                #pragma unroll
                for (int o = tid; o < 1024; o += NT) {
                    int row = o >> 4, c4 = o & 15;
                    float4 x4 = __ldcg((const float4*)&g_invb[p][row * 64 + c4 * 4]);
                    float* d = &sm[OFF_X + row * 65 + c4 * 4];
                    d[0] = x4.x; d[1] = x4.y; d[2] = x4.z; d[3] = x4.w;
                }
            }
            // y4: own 4 Q_ux columns
            {
                int jj = tid >> 6, m = tid & 63;
                sm[OFF_Y4 + jj * 64 + m] = __ldcg(&g_Q[(NX + m) * ND + jb + jj]);
            }
            if (b == 0 && tid < 64) sm[OFF_QU + tid] = __ldcg(&g_q[NX + tid]);
        }
        __syncthreads();

        const float* sX   = &sm[OFF_X];
        const float* sQuu = &sm[OFF_QUU];
        const float* sQxu = &sm[OFF_QXU2];
        const float* sy4  = &sm[OFF_Y4];
        const float* squ  = &sm[OFF_QU];

        if (newton) {
            // S1: W[jj][u] = X y_j ; CTA0 warp0: wq = X q_u
            {
                int u = tid & 63, jj = tid >> 6;
                float s0 = 0.f, s1 = 0.f;
                #pragma unroll 8
                for (int m = 0; m < NU; m += 2) {
                    s0 += sX[u * 65 + m    ] * sy4[jj * 64 + m    ];
                    s1 += sX[u * 65 + m + 1] * sy4[jj * 64 + m + 1];
                }
                Wsh[jj * 64 + u] = s0 + s1;
                if (b == 0 && tid < 32) {
                    #pragma unroll
                    for (int hh = 0; hh < 2; ++hh) {
                        int l = tid + hh * 32;
                        float s = 0.f;
                        #pragma unroll 8
                        for (int m = 0; m < NU; ++m) s += sX[l * 65 + m] * squ[m];
                        wqs[l] = s;
                    }
                }
            }
            __syncthreads();
            // S2: Z = Quu W ; uc = Quu x_c (own cols) ; CTA0: zq = Quu wq
            {
                int r = tid & 63, jj = tid >> 6;
                float s0 = 0.f, s1 = 0.f;
                #pragma unroll 8
                for (int m = 0; m < NU; m += 2) {
                    s0 += sQuu[r * 65 + m    ] * Wsh[jj * 64 + m    ];
                    s1 += sQuu[r * 65 + m + 1] * Wsh[jj * 64 + m + 1];
                }
                Zsh[jj * 64 + r] = s0 + s1;
                if (tid < 128) {
                    int rr = tid & 63, ci = tid >> 6;
                    int cc = c0 + ci;
                    float t0 = 0.f, t1 = 0.f;
                    #pragma unroll 8
                    for (int m = 0; m < NU; m += 2) {
                        t0 += sQuu[rr * 65 + m    ] * sX[(m    ) * 65 + cc];
                        t1 += sQuu[rr * 65 + m + 1] * sX[(m + 1) * 65 + cc];
                    }
                    ush[ci * 64 + rr] = t0 + t1;
                }
                if (b == 0 && tid < 32) {
                    #pragma unroll
                    for (int hh = 0; hh < 2; ++hh) {
                        int l = tid + hh * 32;
                        float s = 0.f;
                        #pragma unroll 8
                        for (int m = 0; m < NU; ++m) s += sQuu[l * 65 + m] * wqs[m];
                        zqs[l] = s;
                    }
                }
            }
            __syncthreads();
            // S3: K = -(2W - X Z) ; X' = 2X - X uc -> g_invb ; CTA0: k = -(2wq - X zq)
            {
                int u = tid & 63, jj = tid >> 6;
                float s0 = 0.f, s1 = 0.f;
                #pragma unroll 8
                for (int m = 0; m < NU; m += 2) {
                    s0 += sX[u * 65 + m    ] * Zsh[jj * 64 + m    ];
                    s1 += sX[u * 65 + m + 1] * Zsh[jj * 64 + m + 1];
                }
                float kv = -(2.0f * Wsh[jj * 64 + u] - (s0 + s1));
                Ksh[u * 4 + jj] = kv;
                g_Ks[(size_t)it * (NU * NX) + u * NX + jb + jj] = kv;
                if (tid < 128) {
                    int rr = tid & 63, ci = tid >> 6;
                    int cc = c0 + ci;
                    float t0 = 0.f, t1 = 0.f;
                    #pragma unroll 8
                    for (int m = 0; m < NU; m += 2) {
                        t0 += sX[rr * 65 + m    ] * ush[ci * 64 + m    ];
                        t1 += sX[rr * 65 + m + 1] * ush[ci * 64 + m + 1];
                    }
                    g_invb[p ^ 1][rr * 64 + cc] = 2.0f * sX[rr * 65 + cc] - (t0 + t1);
                }
                if (b == 0 && tid < 32) {
                    #pragma unroll
                    for (int hh = 0; hh < 2; ++hh) {
                        int l = tid + hh * 32;
                        float s = 0.f;
                        #pragma unroll 8
                        for (int m = 0; m < NU; ++m) s += sX[l * 65 + m] * zqs[m];
                        ksh[l] = -(2.0f * wqs[l] - s);
                    }
                }
            }
            __syncthreads();
        } else {
            // GJ path: K = -X y ; CTA0: k = -X q_u
            {
                int u = tid & 63, jj = tid >> 6;
                float s0 = 0.f, s1 = 0.f;
                #pragma unroll 8
                for (int m = 0; m < NU; m += 2) {
                    s0 += sX[u * 65 + m    ] * sy4[jj * 64 + m    ];
                    s1 += sX[u * 65 + m + 1] * sy4[jj * 64 + m + 1];
                }
                float kv = -(s0 + s1);
                Ksh[u * 4 + jj] = kv;
                g_Ks[(size_t)it * (NU * NX) + u * NX + jb + jj] = kv;
                if (b == 0 && tid < 32) {
                    #pragma unroll
                    for (int hh = 0; hh < 2; ++hh) {
                        int l = tid + hh * 32;
                        float s = 0.f;
                        #pragma unroll 8
                        for (int m = 0; m < NU; ++m) s += sX[l * 65 + m] * squ[m];
                        ksh[l] = -s;
                    }
                }
            }
            __syncthreads();
        }

        // ===== V', M (own 4 cols), v', b, delta =====
        {
            float dmax = 0.f, vmx = 0.f;
            float volds[2] = {vold0, vold1};
            #pragma unroll
            for (int h = 0; h < 2; ++h) {
                const int o = tid + h * NT;
                const int i = o >> 2, jj = o & 3, j = jb + jj;
                float a0 = 0.f, a1 = 0.f, m0 = 0.f, m1 = 0.f;
                #pragma unroll 8
                for (int u = 0; u < NU; u += 2) {
                    float k0 = Ksh[(u    ) * 4 + jj];
                    float k1 = Ksh[(u + 1) * 4 + jj];
                    a0 += sQxu[i * 65 + u    ] * k0;
                    a1 += sQxu[i * 65 + u + 1] * k1;
                    m0 += sFu[i * 65 + u    ] * k0;
                    m1 += sFu[i * 65 + u + 1] * k1;
                }
                float vnew = __ldcg(&g_Q[i * ND + j]) + (a0 + a1);
                Vn[i * NX + j] = vnew;
                dmax = fmaxf(dmax, fabsf(vnew - volds[h]));
                vmx  = fmaxf(vmx, fabsf(vnew));
                g_Ms[(size_t)it * (NX * NX) + i * NX + j] = F[i * ND + j] + (m0 + m1);
            }
            if (b == 0 && tid < NX) {
                float s = 0.f, sb = 0.f;
                #pragma unroll 8
                for (int u = 0; u < NU; ++u) {
                    float kk = ksh[u];
                    s  += sQxu[tid * 65 + u] * kk;
                    sb += sFu[tid * 65 + u] * kk;
                }
                vn[tid] = __ldcg(&g_q[tid]) + s;
                g_bs[it * NX + tid] = f[tid] + sb;
                if (tid < NU) g_ks[it * NU + tid] = ksh[tid];
            }
            #pragma unroll
            for (int o = 16; o > 0; o >>= 1) {
                dmax = fmaxf(dmax, __shfl_down_sync(0xffffffffu, dmax, o));
                vmx  = fmaxf(vmx,  __shfl_down_sync(0xffffffffu, vmx, o));
            }
            if ((tid & 31) == 0) { rmax[tid >> 5] = dmax; rvmx[tid >> 5] = vmx; }
            __syncthreads();
            if (tid == 0) {
                float d = rmax[0], vv = rvmx[0];
                #pragma unroll
                for (int w = 1; w < 8; ++w) { d = fmaxf(d, rmax[w]); vv = fmaxf(vv, rvmx[w]); }
                atomicMax(&g_delta[it], __float_as_uint(d));
                atomicMax(&g_vmax[it], __float_as_uint(vv));
            }
        }
        gbar();   // barrier 2: end of iteration

        {
            float dd = __uint_as_float(__ldcg(&g_delta[it]));
            float vv = __uint_as_float(__ldcg(&g_vmax[it]));
            if (dd <= 1e-6f * vv) {
                if (b == 0 && tid == 0) g_niters = it + 1;
                break;
            }
        }
    }
}

// ---------------- persistent power kernel: copy + 5 affine squarings ----------------
__global__ void __launch_bounds__(256) k_power() {
    const int tid = threadIdx.x;
    {
        const int ni = g_niters;
        const float* src = g_Ms + (size_t)(ni - 1) * (NX * NX);
        for (int o = blockIdx.x * 256 + tid; o < NX * NX; o += PB * 256)
            g_P[0][o] = __ldcg(&src[o]);
        if (blockIdx.x == 16 && tid < NX) g_pb[0][tid] = __ldcg(&g_bs[(ni - 1) * NX + tid]);
    }
    gbar_n(&g_barcnt2, &g_bargen2, PB);

    __shared__ float As[32][33], Bs[32][33];
    #pragma unroll 1
    for (int s = 0; s < 5; ++s) {
        const int p = s & 1;
        const float* Ms = g_P[p];
        const float* bs = g_pb[p];
        float* Md = g_P[p ^ 1];
        float* bd = g_pb[p ^ 1];

        if (blockIdx.x == 16) {
            if (tid < NX) {
                float s0 = 0.f, s1 = 0.f;
                #pragma unroll 8
                for (int k = 0; k < NX; k += 2) {
                    s0 += __ldcg(&Ms[tid * NX + k    ]) * __ldcg(&bs[k    ]);
                    s1 += __ldcg(&Ms[tid * NX + k + 1]) * __ldcg(&bs[k + 1]);
                }
                bd[tid] = (s0 + s1) + __ldcg(&bs[tid]);
            }
        } else {
            const int tr = blockIdx.x >> 2, tc = blockIdx.x & 3;
            const int r  = tid >> 3;
            const int c4 = (tid & 7) * 4;
            float acc0 = 0.f, acc1 = 0.f, acc2 = 0.f, acc3 = 0.f;
            for (int kb = 0; kb < 4; ++kb) {
                #pragma unroll
                for (int l = tid; l < 1024; l += 256) {
                    int lr = l >> 5, lc = l & 31;
                    As[lr][lc] = __ldcg(&Ms[(tr * 32 + lr) * NX + kb * 32 + lc]);
                    Bs[lr][lc] = __ldcg(&Ms[(kb * 32 + lr) * NX + tc * 32 + lc]);
                }
                __syncthreads();
                #pragma unroll
                for (int k = 0; k < 32; ++k) {
                    float av = As[r][k];
                    acc0 += av * Bs[k][c4    ];
                    acc1 += av * Bs[k][c4 + 1];
                    acc2 += av * Bs[k][c4 + 2];
                    acc3 += av * Bs[k][c4 + 3];
                }
                __syncthreads();
            }
            float* dst = Md + (size_t)(tr * 32 + r) * NX + tc * 32 + c4;
            dst[0] = acc0; dst[1] = acc1; dst[2] = acc2; dst[3] = acc3;
        }
        gbar_n(&g_barcnt2, &g_bargen2, PB);
    }
}

// ---------------- segment heads (M^32 chain) + time-varying tail ----------------
__global__ void __launch_bounds__(256) k_heads(const float* __restrict__ x0,
                                               float* __restrict__ out_states) {
    const int tid = threadIdx.x;
    const int row = tid & 127, half = tid >> 7;
    const int ni = g_niters;
    const int tconv = TH - ni;
    const int NS = (tconv + 1) / SEG;
    __shared__ float xs[NX];
    __shared__ float ps[256];

    float mreg[64];
    {
        const float* Mc = g_P[1] + row * NX + half * 64;
        #pragma unroll
        for (int j = 0; j < 64; j += 4) {
            float4 t4 = *(const float4*)(Mc + j);
            mreg[j] = t4.x; mreg[j + 1] = t4.y; mreg[j + 2] = t4.z; mreg[j + 3] = t4.w;
        }
    }
    float breg = g_pb[1][row];

    if (tid < NX) { xs[tid] = x0[tid]; out_states[tid] = x0[tid]; }
    __syncthreads();

    for (int s = 1; s <= NS; ++s) {
        float a0 = 0.f, a1 = 0.f, a2 = 0.f, a3 = 0.f;
        #pragma unroll
        for (int j = 0; j < 64; j += 4) {
            a0 += mreg[j    ] * xs[half * 64 + j    ];
            a1 += mreg[j + 1] * xs[half * 64 + j + 1];
            a2 += mreg[j + 2] * xs[half * 64 + j + 2];
            a3 += mreg[j + 3] * xs[half * 64 + j + 3];
        }
        ps[tid] = (a0 + a1) + (a2 + a3);
        __syncthreads();
        if (half == 0) {
            float xn = ps[row] + ps[128 + row] + breg;
            xs[row] = xn;
            out_states[(size_t)s * SEG * NX + row] = xn;
        }
        __syncthreads();
    }

    {
        const float* Mc = g_Ms + (size_t)(ni - 1) * (NX * NX) + row * NX + half * 64;
        #pragma unroll
        for (int j = 0; j < 64; j += 4) {
            float4 t4 = *(const float4*)(Mc + j);
            mreg[j] = t4.x; mreg[j + 1] = t4.y; mreg[j + 2] = t4.z; mreg[j + 3] = t4.w;
        }
        breg = g_bs[(ni - 1) * NX + row];
    }
    for (int t = NS * SEG; t < TH; ++t) {
        if (t > tconv) {
            const int r = TH - 1 - t;
            const float* Mr = g_Ms + (size_t)r * (NX * NX) + row * NX + half * 64;
            #pragma unroll
            for (int j = 0; j < 64; j += 4) {
                float4 t4 = *(const float4*)(Mr + j);
                mreg[j] = t4.x; mreg[j + 1] = t4.y; mreg[j + 2] = t4.z; mreg[j + 3] = t4.w;
            }
            breg = g_bs[r * NX + row];
        }
        float a0 = 0.f, a1 = 0.f, a2 = 0.f, a3 = 0.f;
        #pragma unroll
        for (int j = 0; j < 64; j += 4) {
            a0 += mreg[j    ] * xs[half * 64 + j    ];
            a1 += mreg[j + 1] * xs[half * 64 + j + 1];
            a2 += mreg[j + 2] * xs[half * 64 + j + 2];
            a3 += mreg[j + 3] * xs[half * 64 + j + 3];
        }
        ps[tid] = (a0 + a1) + (a2 + a3);
        __syncthreads();
        if (half == 0) {
            float xn = ps[row] + ps[128 + row] + breg;
            xs[row] = xn;
            out_states[(size_t)(t + 1) * NX + row] = xn;
        }
        __syncthreads();
    }
}

// ---------------- parallel segment fill ----------------
__global__ void __launch_bounds__(256) k_fill(float* __restrict__ out_states) {
    const int s = blockIdx.x;
    const int tid = threadIdx.x;
    const int row = tid & 127, half = tid >> 7;
    const int ni = g_niters;
    const int tconv = TH - ni;
    const int NS = (tconv + 1) / SEG;
    if (s >= NS) return;
    __shared__ float xs[NX];
    __shared__ float ps[256];

    float mreg[64];
    {
        const float* Mc = g_Ms + (size_t)(ni - 1) * (NX * NX) + row * NX + half * 64;
        #pragma unroll
        for (int j = 0; j < 64; j += 4) {
            float4 t4 = *(const float4*)(Mc + j);
            mreg[j] = t4.x; mreg[j + 1] = t4.y; mreg[j + 2] = t4.z; mreg[j + 3] = t4.w;
        }
    }
    float breg = g_bs[(ni - 1) * NX + row];

    if (tid < NX) xs[tid] = out_states[(size_t)s * SEG * NX + tid];
    __syncthreads();

    #pragma unroll 1
    for (int j2 = 1; j2 < SEG; ++j2) {
        float a0 = 0.f, a1 = 0.f, a2 = 0.f, a3 = 0.f;
        #pragma unroll
        for (int j = 0; j < 64; j += 4) {
            a0 += mreg[j    ] * xs[half * 64 + j    ];
            a1 += mreg[j + 1] * xs[half * 64 + j + 1];
            a2 += mreg[j + 2] * xs[half * 64 + j + 2];
            a3 += mreg[j + 3] * xs[half * 64 + j + 3];
        }
        ps[tid] = (a0 + a1) + (a2 + a3);
        __syncthreads();
        if (half == 0) {
            float xn = ps[row] + ps[128 + row] + breg;
            xs[row] = xn;
            out_states[(size_t)(s * SEG + j2) * NX + row] = xn;
        }
        __syncthreads();
    }
}

// ---------------- epilogue: 4 timesteps per block ----------------
__global__ void __launch_bounds__(192) k_epilogue(const float* __restrict__ C,
                                                  const float* __restrict__ c,
                                                  const float* __restrict__ states,
                                                  float* __restrict__ us,
                                                  float* __restrict__ costs) {
    const int t0 = blockIdx.x * 4, tid = threadIdx.x;
    const int ni = g_niters;
    __shared__ float zs[4][ND];
    __shared__ float red[192];

    #pragma unroll
    for (int k = 0; k < 4; ++k) {
        int t = t0 + k;
        if (tid < NX) zs[k][tid] = (t <= TH) ? states[(size_t)t * NX + tid] : 0.0f;
        else zs[k][tid] = 0.0f;
    }
    __syncthreads();

    if (tid < NU) {
        #pragma unroll
        for (int k = 0; k < 4; ++k) {
            int t = t0 + k;
            if (t < TH) {
                int r = TH - 1 - t; if (r > ni - 1) r = ni - 1;
                const float* Kr = g_Ks + (size_t)r * (NU * NX) + tid * NX;
                float a0 = 0.f, a1 = 0.f, a2 = 0.f, a3 = 0.f;
                #pragma unroll 8
                for (int j = 0; j < NX; j += 4) {
                    a0 += Kr[j    ] * zs[k][j    ];
                    a1 += Kr[j + 1] * zs[k][j + 1];
                    a2 += Kr[j + 2] * zs[k][j + 2];
                    a3 += Kr[j + 3] * zs[k][j + 3];
                }
                float u = g_ks[r * NU + tid] + (a0 + a1) + (a2 + a3);
                zs[k][NX + tid] = u;
                us[(size_t)t * NU + tid] = u;
            }
        }
    }
    __syncthreads();

    float cz0 = 0.f, cz1 = 0.f, cz2 = 0.f, cz3 = 0.f;
    #pragma unroll 4
    for (int i = 0; i < ND; ++i) {
        float Cv = C[i * ND + tid];
        cz0 += zs[0][i] * Cv;
        cz1 += zs[1][i] * Cv;
        cz2 += zs[2][i] * Cv;
        cz3 += zs[3][i] * Cv;
    }
    const float cv = c[tid];
    float val[4];
    val[0] = zs[0][tid] * (0.5f * cz0 + cv);
    val[1] = zs[1][tid] * (0.5f * cz1 + cv);
    val[2] = zs[2][tid] * (0.5f * cz2 + cv);
    val[3] = zs[3][tid] * (0.5f * cz3 + cv);

    #pragma unroll
    for (int k = 0; k < 4; ++k) {
        __syncthreads();
        red[tid] = val[k];
        __syncthreads();
        #pragma unroll
        for (int s = 96; s >= 6; s >>= 1) {
            if (tid < s) red[tid] += red[tid + s];
            __syncthreads();
        }
        int t = t0 + k;
        if (tid == 0 && t <= TH)
            costs[t] = red[0] + red[1] + red[2] + red[3] + red[4] + red[5];
    }
}

// ---------------- launch ----------------
extern "C" void kernel_launch(void* const* d_in, const int* in_sizes, int n_in,
                              void* d_out, int out_size) {
    const float* F  = (const float*)d_in[0];
    const float* f  = (const float*)d_in[1];
    const float* C  = (const float*)d_in[2];
    const float* c  = (const float*)d_in[3];
    const float* x0 = (const float*)d_in[4];
    (void)in_sizes; (void)n_in; (void)out_size;

    float* out        = (float*)d_out;
    float* out_states = out;
    float* out_us     = out + (size_t)(TH + 1) * NX;
    float* out_costs  = out_us + (size_t)TH * NU;

    cudaFuncSetAttribute(k_backward, cudaFuncAttributeMaxDynamicSharedMemorySize, SMEM_BK);

    k_setup<<<96, NT>>>(F, C, c);
    k_backward<<<GB, NT, SMEM_BK>>>(F, f, C, c);
    k_power<<<PB, 256>>>();
    k_heads<<<1, 256>>>(x0, out_states);
    k_fill<<<64, 256>>>(out_states);
    k_epilogue<<<(TH + 4) / 4, 192>>>(C, c, out_states, out_us, out_costs);
}

// round 15
// speedup vs baseline: 1.6919x; 1.1007x over previous
#include <cuda_runtime.h>
#include <cstdint>

#define NX 128
#define NU 64
#define ND 192
#define TH 2048
#define GB 32
#define NT 256
#define RPB 6
#define SEG 32
#define IT_SW 32
#define PB 17

// dynamic smem layout (float offsets)
#define OFF_FU   0        // 128x64 (pitch 64)  F_u, staged once
#define OFF_QUU  8192     // 64x64
#define OFF_X    12288    // 64x64 row-major
#define OFF_XT   16384    // 64x64 transposed
#define OFF_QXU  8192     // 128x64, staged AFTER S3 (overwrites QUU+X)
#define OFF_Y4   20480    // 4x64
#define OFF_QU   20736    // 64
#define SMEM_FLOATS 20800
#define SMEM_BK (SMEM_FLOATS * 4)

__device__ __align__(16) float g_Ft[ND * NX];
__device__ __align__(16) float g_Vb[2][NX * NX];
__device__ __align__(16) float g_vb[2][NX];
__device__ __align__(16) float g_Q[ND * ND];
__device__ __align__(16) float g_q[ND];
__device__ __align__(16) float g_invb[2][NU * NU];
__device__ __align__(16) float g_invbT[2][NU * NU];
__device__ __align__(16) float g_Ks[(size_t)TH * NU * NX];
__device__ __align__(16) float g_ks[TH * NU];
__device__ __align__(16) float g_Ms[(size_t)TH * NX * NX];
__device__ __align__(16) float g_bs[TH * NX];
__device__ __align__(16) float g_P[2][NX * NX];
__device__ __align__(16) float g_pb[2][NX];
__device__ unsigned g_delta[TH];
__device__ unsigned g_vmax[TH];
__device__ int g_niters;
__device__ unsigned g_barcnt = 0;
__device__ unsigned g_bargen = 0;
__device__ unsigned g_barcnt2 = 0;
__device__ unsigned g_bargen2 = 0;

__device__ __forceinline__ void gbar_n(unsigned* cnt, unsigned* gen_p, unsigned nb) {
    __syncthreads();
    if (threadIdx.x == 0) {
        __threadfence();
        volatile unsigned* vg = gen_p;
        unsigned gen = *vg;
        if (atomicAdd(cnt, 1u) == nb - 1) {
            *cnt = 0u;
            __threadfence();
            atomicAdd(gen_p, 1u);
        } else {
            while (*vg == gen) {}
        }
        __threadfence();
    }
    __syncthreads();
}
__device__ __forceinline__ void gbar() { gbar_n(&g_barcnt, &g_bargen, GB); }

__global__ void k_nop() {}

__global__ void __launch_bounds__(NT) k_setup(const float* __restrict__ F,
                                              const float* __restrict__ C,
                                              const float* __restrict__ c) {
    int idx = blockIdx.x * NT + threadIdx.x;
    if (idx < ND * NX) {
        int i = idx / NX, m = idx - i * NX;
        g_Ft[i * NX + m] = F[m * ND + i];
    }
    if (idx < NX * NX) {
        int i = idx >> 7, j = idx & 127;
        g_Vb[0][idx] = C[i * ND + j];
    }
    if (idx < NX) g_vb[0][idx] = c[idx];
    if (idx < TH) { g_delta[idx] = 0u; g_vmax[idx] = 0u; }
    if (idx == 0) g_niters = TH;
}

// ---------------- backward Riccati (persistent, 32 CTAs, 2 barriers/iter) ----------------
__global__ void __launch_bounds__(NT) k_backward(const float* __restrict__ F,
                                                 const float* __restrict__ f,
                                                 const float* __restrict__ C,
                                                 const float* __restrict__ c) {
    const int b = blockIdx.x, tid = threadIdx.x;
    const int jb = b * 4;          // owned K / V' / M columns
    const int c0 = b * 2;          // owned X' columns
    extern __shared__ float sm[];

    __shared__ __align__(16) float ft6[6][NX];
    __shared__ __align__(16) float fv6[6][NX];
    __shared__ __align__(16) float pf2[2 * 6 * NX];
    __shared__ __align__(16) float prA[64], prI[64], fsh[64];
    __shared__ float pivsh;
    __shared__ float rmax[8], rvmx[8];
    __shared__ __align__(16) float Wsh[256];
    __shared__ __align__(16) float Zsh[256];
    __shared__ __align__(16) float ush[128];
    __shared__ __align__(16) float wqs[64];
    __shared__ __align__(16) float zqs[64];
    __shared__ __align__(16) float ksh[64];
    __shared__ __align__(16) float Ksh[256];     // [u*4 + jj]

    // stage F_u once into dynamic smem (pitch 64)
    for (int o = tid; o < 128 * 64; o += NT) {
        int i = o >> 6, u = o & 63;
        sm[OFF_FU + i * 64 + u] = F[i * ND + NX + u];
    }
    __syncthreads();

    for (int it = 0; it < TH; ++it) {
        const int p = it & 1;
        const bool newton = (it >= IT_SW);
        const float* V  = g_Vb[p];
        const float* v  = g_vb[p];
        float* Vn = g_Vb[p ^ 1];
        float* vn = g_vb[p ^ 1];
        const int i0 = b * RPB;

        // ===== phase 1: register-blocked Q build (one pass, 6 rows) =====
        for (int o = tid; o < 6 * NX; o += NT) {
            int r = o >> 7, k = o & 127;
            ft6[r][k] = g_Ft[(i0 + r) * NX + k];
        }
        __syncthreads();
        {
            // FV partials: thread (m, k-half g)
            const int m = tid & 127, g = tid >> 7;
            float a0 = 0.f, a1 = 0.f, a2 = 0.f, a3 = 0.f, a4 = 0.f, a5 = 0.f;
            const float* Vg = V + (g * 64) * NX + m;
            #pragma unroll 4
            for (int k = 0; k < 64; k += 4) {
                float v0 = __ldcg(Vg + (k    ) * NX);
                float v1 = __ldcg(Vg + (k + 1) * NX);
                float v2 = __ldcg(Vg + (k + 2) * NX);
                float v3 = __ldcg(Vg + (k + 3) * NX);
                #pragma unroll
                for (int r = 0; r < 6; ++r) {
                    float4 fr = *(const float4*)&ft6[r][g * 64 + k];
                    float t = fr.x * v0 + fr.y * v1 + fr.z * v2 + fr.w * v3;
                    if (r == 0) a0 += t; else if (r == 1) a1 += t;
                    else if (r == 2) a2 += t; else if (r == 3) a3 += t;
                    else if (r == 4) a4 += t; else a5 += t;
                }
            }
            pf2[g * 768 + 0 * 128 + m] = a0;
            pf2[g * 768 + 1 * 128 + m] = a1;
            pf2[g * 768 + 2 * 128 + m] = a2;
            pf2[g * 768 + 3 * 128 + m] = a3;
            pf2[g * 768 + 4 * 128 + m] = a4;
            pf2[g * 768 + 5 * 128 + m] = a5;
        }
        __syncthreads();
        {
            float* fv6f = &fv6[0][0];
            for (int o = tid; o < 768; o += NT) fv6f[o] = pf2[o] + pf2[768 + o];
        }
        __syncthreads();
        // q rows
        if (tid < 192) {
            int r = tid >> 5, lane = tid & 31;
            float s = 0.f;
            #pragma unroll
            for (int m = lane; m < 128; m += 32)
                s += fv6[r][m] * f[m] + ft6[r][m] * __ldcg(&v[m]);
            #pragma unroll
            for (int o = 16; o > 0; o >>= 1) s += __shfl_down_sync(0xffffffffu, s, o);
            if (lane == 0) g_q[i0 + r] = c[i0 + r] + s;
        }
        // Q rows (6-row register blocked over F reads)
        if (tid < ND) {
            const int j = tid;
            float acc[6];
            #pragma unroll
            for (int r = 0; r < 6; ++r) acc[r] = C[(i0 + r) * ND + j];
            #pragma unroll 4
            for (int mm = 0; mm < 128; mm += 4) {
                float s0 = F[(mm    ) * ND + j];
                float s1 = F[(mm + 1) * ND + j];
                float s2 = F[(mm + 2) * ND + j];
                float s3 = F[(mm + 3) * ND + j];
                #pragma unroll
                for (int r = 0; r < 6; ++r) {
                    float4 fr = *(const float4*)&fv6[r][mm];
                    acc[r] += fr.x * s0 + fr.y * s1 + fr.z * s2 + fr.w * s3;
                }
            }
            #pragma unroll
            for (int r = 0; r < 6; ++r) g_Q[(i0 + r) * ND + j] = acc[r];
        }
        gbar();   // barrier 1: Q ready

        // old V values for delta (f4, own 4 columns)
        float4 vold4;
        if (tid < 128) vold4 = __ldcg((const float4*)&V[tid * NX + jb]);

        // ===== produce X (row) + Xt (transposed) in smem =====
        if (!newton) {
            // register Gauss-Jordan, every CTA
            const int r = tid >> 2, q4 = tid & 3;
            float ar[16], vi[16];
            #pragma unroll
            for (int jj = 0; jj < 16; ++jj) {
                int col = q4 * 16 + jj;
                ar[jj] = __ldcg(&g_Q[(NX + r) * ND + NX + col]);
                vi[jj] = (col == r) ? 1.0f : 0.0f;
            }
            #pragma unroll 1
            for (int pv = 0; pv < 64; ++pv) {
                const int ps = pv >> 4, pj = pv & 15;
                if (r == pv && q4 == ps) pivsh = 1.0f / ar[pj];
                __syncthreads();
                const float pvv = pivsh;
                if (r == pv) {
                    #pragma unroll
                    for (int jj = 0; jj < 16; ++jj) {
                        ar[jj] *= pvv; vi[jj] *= pvv;
                        prA[q4 * 16 + jj] = ar[jj];
                        prI[q4 * 16 + jj] = vi[jj];
                    }
                }
                if (q4 == ps) fsh[r] = ar[pj];
                __syncthreads();
                if (r != pv) {
                    const float fr = fsh[r];
                    #pragma unroll
                    for (int jj = 0; jj < 16; ++jj) {
                        ar[jj] -= fr * prA[q4 * 16 + jj];
                        vi[jj] -= fr * prI[q4 * 16 + jj];
                    }
                }
                __syncthreads();
            }
            #pragma unroll
            for (int jj = 0; jj < 16; ++jj) {
                int col = q4 * 16 + jj;
                sm[OFF_X  + r * 64 + col] = vi[jj];
                sm[OFF_XT + col * 64 + r] = vi[jj];
                if (b == 0) {
                    g_invb[p ^ 1][r * 64 + col]  = vi[jj];
                    g_invbT[p ^ 1][col * 64 + r] = vi[jj];
                }
            }
        } else {
            // bulk-stage QUU, X, Xt
            #pragma unroll
            for (int o = tid; o < 1024; o += NT) {
                int row = o >> 4, c4 = o & 15;
                float4 q4v = __ldcg((const float4*)&g_Q[(NX + row) * ND + NX + c4 * 4]);
                *(float4*)&sm[OFF_QUU + row * 64 + c4 * 4] = q4v;
            }
            #pragma unroll
            for (int o = tid; o < 1024; o += NT) {
                float4 x4 = __ldcg((const float4*)&g_invb[p][o * 4]);
                *(float4*)&sm[OFF_X + o * 4] = x4;
            }
            #pragma unroll
            for (int o = tid; o < 1024; o += NT) {
                float4 x4 = __ldcg((const float4*)&g_invbT[p][o * 4]);
                *(float4*)&sm[OFF_XT + o * 4] = x4;
            }
        }
        // y4 (own 4 Q_ux columns), qu (CTA0)
        {
            int jj = tid >> 6, m = tid & 63;
            sm[OFF_Y4 + jj * 64 + m] = __ldcg(&g_Q[(NX + m) * ND + jb + jj]);
        }
        if (b == 0 && tid < 64) sm[OFF_QU + tid] = __ldcg(&g_q[NX + tid]);
        __syncthreads();

        // ===== S1: W = X y ; b0: wq = X qu =====
        {
            int u = tid & 63, jj = tid >> 6;
            float s = 0.f;
            #pragma unroll 4
            for (int mq = 0; mq < 64; mq += 4) {
                float4 x4 = *(const float4*)&sm[OFF_X + u * 64 + mq];
                float4 y4 = *(const float4*)&sm[OFF_Y4 + jj * 64 + mq];
                s += x4.x * y4.x + x4.y * y4.y + x4.z * y4.z + x4.w * y4.w;
            }
            Wsh[jj * 64 + u] = s;
            if (b == 0 && tid < 64) {
                float t = 0.f;
                #pragma unroll 4
                for (int mq = 0; mq < 64; mq += 4) {
                    float4 x4 = *(const float4*)&sm[OFF_X + tid * 64 + mq];
                    float4 q4 = *(const float4*)&sm[OFF_QU + mq];
                    t += x4.x * q4.x + x4.y * q4.y + x4.z * q4.z + x4.w * q4.w;
                }
                wqs[tid] = t;
            }
        }
        __syncthreads();

        if (!newton) {
            // K = -W, k = -wq
            int u = tid & 63, jj = tid >> 6;
            float kv = -Wsh[jj * 64 + u];
            Ksh[u * 4 + jj] = kv;
            g_Ks[(size_t)it * (NU * NX) + u * NX + jb + jj] = kv;
            if (b == 0 && tid < 64) ksh[tid] = -wqs[tid];
        } else {
            // S2: Z = Quu W ; ush = Quu x_cc ; b0: zq = Quu wq
            {
                int r = tid & 63, jj = tid >> 6;
                float s = 0.f;
                #pragma unroll 4
                for (int mq = 0; mq < 64; mq += 4) {
                    float4 q4 = *(const float4*)&sm[OFF_QUU + r * 64 + mq];
                    float4 w4 = *(const float4*)&Wsh[jj * 64 + mq];
                    s += q4.x * w4.x + q4.y * w4.y + q4.z * w4.z + q4.w * w4.w;
                }
                Zsh[jj * 64 + r] = s;
                if (tid < 128) {
                    int rr = tid & 63, ci = tid >> 6, cc = c0 + ci;
                    float t = 0.f;
                    #pragma unroll 4
                    for (int mq = 0; mq < 64; mq += 4) {
                        float4 q4 = *(const float4*)&sm[OFF_QUU + rr * 64 + mq];
                        float4 x4 = *(const float4*)&sm[OFF_XT + cc * 64 + mq];
                        t += q4.x * x4.x + q4.y * x4.y + q4.z * x4.z + q4.w * x4.w;
                    }
                    ush[ci * 64 + rr] = t;
                }
                if (b == 0 && tid < 64) {
                    float t = 0.f;
                    #pragma unroll 4
                    for (int mq = 0; mq < 64; mq += 4) {
                        float4 q4 = *(const float4*)&sm[OFF_QUU + tid * 64 + mq];
                        float4 w4 = *(const float4*)&wqs[mq];
                        t += q4.x * w4.x + q4.y * w4.y + q4.z * w4.z + q4.w * w4.w;
                    }
                    zqs[tid] = t;
                }
            }
            __syncthreads();
            // S3: K = -(2W - X Z) ; X' = 2X - X ush ; b0: k
            {
                int u = tid & 63, jj = tid >> 6;
                float s = 0.f;
                #pragma unroll 4
                for (int mq = 0; mq < 64; mq += 4) {
                    float4 x4 = *(const float4*)&sm[OFF_X + u * 64 + mq];
                    float4 z4 = *(const float4*)&Zsh[jj * 64 + mq];
                    s += x4.x * z4.x + x4.y * z4.y + x4.z * z4.z + x4.w * z4.w;
                }
                float kv = -(2.0f * Wsh[jj * 64 + u] - s);
                Ksh[u * 4 + jj] = kv;
                g_Ks[(size_t)it * (NU * NX) + u * NX + jb + jj] = kv;
                if (tid < 128) {
                    int rr = tid & 63, ci = tid >> 6, cc = c0 + ci;
                    float t = 0.f;
                    #pragma unroll 4
                    for (int mq = 0; mq < 64; mq += 4) {
                        float4 x4 = *(const float4*)&sm[OFF_X + rr * 64 + mq];
                        float4 u4 = *(const float4*)&ush[ci * 64 + mq];
                        t += x4.x * u4.x + x4.y * u4.y + x4.z * u4.z + x4.w * u4.w;
                    }
                    float xn = 2.0f * sm[OFF_X + rr * 64 + cc] - t;
                    g_invb[p ^ 1][rr * 64 + cc]  = xn;
                    g_invbT[p ^ 1][cc * 64 + rr] = xn;
                }
                if (b == 0 && tid < 64) {
                    float t = 0.f;
                    #pragma unroll 4
                    for (int mq = 0; mq < 64; mq += 4) {
                        float4 x4 = *(const float4*)&sm[OFF_X + tid * 64 + mq];
                        float4 z4 = *(const float4*)&zqs[mq];
                        t += x4.x * z4.x + x4.y * z4.y + x4.z * z4.z + x4.w * z4.w;
                    }
                    ksh[tid] = -(2.0f * wqs[tid] - t);
                }
            }
        }
        __syncthreads();

        // stage Q_xu (overwrites QUU+X region; X/Xt dead now)
        #pragma unroll
        for (int o = tid; o < 2048; o += NT) {
            int row = o >> 4, c4 = o & 15;
            float4 q4v = __ldcg((const float4*)&g_Q[row * ND + NX + c4 * 4]);
            *(float4*)&sm[OFF_QXU + row * 64 + c4 * 4] = q4v;
        }
        __syncthreads();

        // ===== V' (t<128) and M (t>=128), 4 columns each; v', b; delta =====
        {
            float dmax = 0.f, vmx = 0.f;
            const int i = tid & 127;
            const bool doM = tid >= 128;
            const int base = (doM ? OFF_FU : OFF_QXU) + i * 64;
            float a0 = 0.f, a1 = 0.f, a2 = 0.f, a3 = 0.f;
            #pragma unroll 4
            for (int uq = 0; uq < 64; uq += 4) {
                float4 s4 = *(const float4*)&sm[base + uq];
                float4 k0 = *(const float4*)&Ksh[(uq    ) * 4];
                float4 k1 = *(const float4*)&Ksh[(uq + 1) * 4];
                float4 k2 = *(const float4*)&Ksh[(uq + 2) * 4];
                float4 k3 = *(const float4*)&Ksh[(uq + 3) * 4];
                a0 += s4.x * k0.x + s4.y * k1.x + s4.z * k2.x + s4.w * k3.x;
                a1 += s4.x * k0.y + s4.y * k1.y + s4.z * k2.y + s4.w * k3.y;
                a2 += s4.x * k0.z + s4.y * k1.z + s4.z * k2.z + s4.w * k3.z;
                a3 += s4.x * k0.w + s4.y * k1.w + s4.z * k2.w + s4.w * k3.w;
            }
            if (!doM) {
                float4 qx = __ldcg((const float4*)&g_Q[i * ND + jb]);
                float4 vnewv;
                vnewv.x = qx.x + a0; vnewv.y = qx.y + a1;
                vnewv.z = qx.z + a2; vnewv.w = qx.w + a3;
                *(float4*)&Vn[i * NX + jb] = vnewv;
                dmax = fmaxf(fmaxf(fabsf(vnewv.x - vold4.x), fabsf(vnewv.y - vold4.y)),
                             fmaxf(fabsf(vnewv.z - vold4.z), fabsf(vnewv.w - vold4.w)));
                vmx  = fmaxf(fmaxf(fabsf(vnewv.x), fabsf(vnewv.y)),
                             fmaxf(fabsf(vnewv.z), fabsf(vnewv.w)));
            } else {
                float4 fx;
                fx.x = F[i * ND + jb    ];
                fx.y = F[i * ND + jb + 1];
                fx.z = F[i * ND + jb + 2];
                fx.w = F[i * ND + jb + 3];
                float4 mv;
                mv.x = fx.x + a0; mv.y = fx.y + a1;
                mv.z = fx.z + a2; mv.w = fx.w + a3;
                *(float4*)&g_Ms[(size_t)it * (NX * NX) + i * NX + jb] = mv;
            }
            if (b == 0) {
                // v' and b (CTA0): i-row dot with ksh
                float s = 0.f, sb = 0.f;
                #pragma unroll 4
                for (int uq = 0; uq < 64; uq += 4) {
                    float4 k4 = *(const float4*)&ksh[uq];
                    float4 qx4 = *(const float4*)&sm[OFF_QXU + i * 64 + uq];
                    float4 fu4 = *(const float4*)&sm[OFF_FU + i * 64 + uq];
                    s  += qx4.x * k4.x + qx4.y * k4.y + qx4.z * k4.z + qx4.w * k4.w;
                    sb += fu4.x * k4.x + fu4.y * k4.y + fu4.z * k4.z + fu4.w * k4.w;
                }
                if (!doM) {
                    vn[i] = __ldcg(&g_q[i]) + s;
                    g_bs[it * NX + i] = f[i] + sb;
                    if (i < NU) g_ks[it * NU + i] = ksh[i];
                }
            }
            #pragma unroll
            for (int o = 16; o > 0; o >>= 1) {
                dmax = fmaxf(dmax, __shfl_down_sync(0xffffffffu, dmax, o));
                vmx  = fmaxf(vmx,  __shfl_down_sync(0xffffffffu, vmx, o));
            }
            if ((tid & 31) == 0) { rmax[tid >> 5] = dmax; rvmx[tid >> 5] = vmx; }
            __syncthreads();
            if (tid == 0) {
                float d = rmax[0], vv = rvmx[0];
                #pragma unroll
                for (int w = 1; w < 8; ++w) { d = fmaxf(d, rmax[w]); vv = fmaxf(vv, rvmx[w]); }
                atomicMax(&g_delta[it], __float_as_uint(d));
                atomicMax(&g_vmax[it], __float_as_uint(vv));
            }
        }
        gbar();   // barrier 2: end of iteration

        {
            float dd = __uint_as_float(__ldcg(&g_delta[it]));
            float vv = __uint_as_float(__ldcg(&g_vmax[it]));
            if (dd <= 1e-6f * vv) {
                if (b == 0 && tid == 0) g_niters = it + 1;
                break;
            }
        }
    }
}

// ---------------- persistent power kernel: copy + 5 affine squarings ----------------
__global__ void __launch_bounds__(256) k_power() {
    const int tid = threadIdx.x;
    {
        const int ni = g_niters;
        const float* src = g_Ms + (size_t)(ni - 1) * (NX * NX);
        for (int o = blockIdx.x * 256 + tid; o < NX * NX; o += PB * 256)
            g_P[0][o] = __ldcg(&src[o]);
        if (blockIdx.x == 16 && tid < NX) g_pb[0][tid] = __ldcg(&g_bs[(ni - 1) * NX + tid]);
    }
    gbar_n(&g_barcnt2, &g_bargen2, PB);

    __shared__ __align__(16) float As[32][33];
    __shared__ __align__(16) float Bs[32][33];
    #pragma unroll 1
    for (int s = 0; s < 5; ++s) {
        const int p = s & 1;
        const float* Ms = g_P[p];
        const float* bs = g_pb[p];
        float* Md = g_P[p ^ 1];
        float* bd = g_pb[p ^ 1];

        if (blockIdx.x == 16) {
            if (tid < NX) {
                float s0 = 0.f, s1 = 0.f;
                #pragma unroll 8
                for (int k = 0; k < NX; k += 2) {
                    s0 += __ldcg(&Ms[tid * NX + k    ]) * __ldcg(&bs[k    ]);
                    s1 += __ldcg(&Ms[tid * NX + k + 1]) * __ldcg(&bs[k + 1]);
                }
                bd[tid] = (s0 + s1) + __ldcg(&bs[tid]);
            }
        } else {
            const int tr = blockIdx.x >> 2, tc = blockIdx.x & 3;
            const int r  = tid >> 3;
            const int c4 = (tid & 7) * 4;
            float acc0 = 0.f, acc1 = 0.f, acc2 = 0.f, acc3 = 0.f;
            for (int kb = 0; kb < 4; ++kb) {
                #pragma unroll
                for (int l = tid; l < 1024; l += 256) {
                    int lr = l >> 5, lc = l & 31;
                    As[lr][lc] = __ldcg(&Ms[(tr * 32 + lr) * NX + kb * 32 + lc]);
                    Bs[lr][lc] = __ldcg(&Ms[(kb * 32 + lr) * NX + tc * 32 + lc]);
                }
                __syncthreads();
                #pragma unroll
                for (int k = 0; k < 32; ++k) {
                    float av = As[r][k];
                    acc0 += av * Bs[k][c4    ];
                    acc1 += av * Bs[k][c4 + 1];
                    acc2 += av * Bs[k][c4 + 2];
                    acc3 += av * Bs[k][c4 + 3];
                }
                __syncthreads();
            }
            float* dst = Md + (size_t)(tr * 32 + r) * NX + tc * 32 + c4;
            dst[0] = acc0; dst[1] = acc1; dst[2] = acc2; dst[3] = acc3;
        }
        gbar_n(&g_barcnt2, &g_bargen2, PB);
    }
}

// ---------------- segment heads (M^32 chain) + time-varying tail ----------------
__global__ void __launch_bounds__(256) k_heads(const float* __restrict__ x0,
                                               float* __restrict__ out_states) {
    const int tid = threadIdx.x;
    const int row = tid & 127, half = tid >> 7;
    const int ni = g_niters;
    const int tconv = TH - ni;
    const int NS = (tconv + 1) / SEG;
    __shared__ __align__(16) float xs[NX];
    __shared__ __align__(16) float ps[256];

    float mreg[64];
    {
        const float* Mc = g_P[1] + row * NX + half * 64;
        #pragma unroll
        for (int j = 0; j < 64; j += 4) {
            float4 t4 = *(const float4*)(Mc + j);
            mreg[j] = t4.x; mreg[j + 1] = t4.y; mreg[j + 2] = t4.z; mreg[j + 3] = t4.w;
        }
    }
    float breg = g_pb[1][row];

    if (tid < NX) { xs[tid] = x0[tid]; out_states[tid] = x0[tid]; }
    __syncthreads();

    for (int s = 1; s <= NS; ++s) {
        float a0 = 0.f, a1 = 0.f, a2 = 0.f, a3 = 0.f;
        #pragma unroll
        for (int j = 0; j < 64; j += 4) {
            a0 += mreg[j    ] * xs[half * 64 + j    ];
            a1 += mreg[j + 1] * xs[half * 64 + j + 1];
            a2 += mreg[j + 2] * xs[half * 64 + j + 2];
            a3 += mreg[j + 3] * xs[half * 64 + j + 3];
        }
        ps[tid] = (a0 + a1) + (a2 + a3);
        __syncthreads();
        if (half == 0) {
            float xn = ps[row] + ps[128 + row] + breg;
            xs[row] = xn;
            out_states[(size_t)s * SEG * NX + row] = xn;
        }
        __syncthreads();
    }

    {
        const float* Mc = g_Ms + (size_t)(ni - 1) * (NX * NX) + row * NX + half * 64;
        #pragma unroll
        for (int j = 0; j < 64; j += 4) {
            float4 t4 = *(const float4*)(Mc + j);
            mreg[j] = t4.x; mreg[j + 1] = t4.y; mreg[j + 2] = t4.z; mreg[j + 3] = t4.w;
        }
        breg = g_bs[(ni - 1) * NX + row];
    }
    for (int t = NS * SEG; t < TH; ++t) {
        if (t > tconv) {
            const int r = TH - 1 - t;
            const float* Mr = g_Ms + (size_t)r * (NX * NX) + row * NX + half * 64;
            #pragma unroll
            for (int j = 0; j < 64; j += 4) {
                float4 t4 = *(const float4*)(Mr + j);
                mreg[j] = t4.x; mreg[j + 1] = t4.y; mreg[j + 2] = t4.z; mreg[j + 3] = t4.w;
            }
            breg = g_bs[r * NX + row];
        }
        float a0 = 0.f, a1 = 0.f, a2 = 0.f, a3 = 0.f;
        #pragma unroll
        for (int j = 0; j < 64; j += 4) {
            a0 += mreg[j    ] * xs[half * 64 + j    ];
            a1 += mreg[j + 1] * xs[half * 64 + j + 1];
            a2 += mreg[j + 2] * xs[half * 64 + j + 2];
            a3 += mreg[j + 3] * xs[half * 64 + j + 3];
        }
        ps[tid] = (a0 + a1) + (a2 + a3);
        __syncthreads();
        if (half == 0) {
            float xn = ps[row] + ps[128 + row] + breg;
            xs[row] = xn;
            out_states[(size_t)(t + 1) * NX + row] = xn;
        }
        __syncthreads();
    }
}

// ---------------- parallel segment fill ----------------
__global__ void __launch_bounds__(256) k_fill(float* __restrict__ out_states) {
    const int s = blockIdx.x;
    const int tid = threadIdx.x;
    const int row = tid & 127, half = tid >> 7;
    const int ni = g_niters;
    const int tconv = TH - ni;
    const int NS = (tconv + 1) / SEG;
    if (s >= NS) return;
    __shared__ __align__(16) float xs[NX];
    __shared__ __align__(16) float ps[256];

    float mreg[64];
    {
        const float* Mc = g_Ms + (size_t)(ni - 1) * (NX * NX) + row * NX + half * 64;
        #pragma unroll
        for (int j = 0; j < 64; j += 4) {
            float4 t4 = *(const float4*)(Mc + j);
            mreg[j] = t4.x; mreg[j + 1] = t4.y; mreg[j + 2] = t4.z; mreg[j + 3] = t4.w;
        }
    }
    float breg = g_bs[(ni - 1) * NX + row];

    if (tid < NX) xs[tid] = out_states[(size_t)s * SEG * NX + tid];
    __syncthreads();

    #pragma unroll 1
    for (int j2 = 1; j2 < SEG; ++j2) {
        float a0 = 0.f, a1 = 0.f, a2 = 0.f, a3 = 0.f;
        #pragma unroll
        for (int j = 0; j < 64; j += 4) {
            a0 += mreg[j    ] * xs[half * 64 + j    ];
            a1 += mreg[j + 1] * xs[half * 64 + j + 1];
            a2 += mreg[j + 2] * xs[half * 64 + j + 2];
            a3 += mreg[j + 3] * xs[half * 64 + j + 3];
        }
        ps[tid] = (a0 + a1) + (a2 + a3);
        __syncthreads();
        if (half == 0) {
            float xn = ps[row] + ps[128 + row] + breg;
            xs[row] = xn;
            out_states[(size_t)(s * SEG + j2) * NX + row] = xn;
        }
        __syncthreads();
    }
}

// ---------------- epilogue: 4 timesteps per block ----------------
__global__ void __launch_bounds__(192) k_epilogue(const float* __restrict__ C,
                                                  const float* __restrict__ c,
                                                  const float* __restrict__ states,
                                                  float* __restrict__ us,
                                                  float* __restrict__ costs) {
    const int t0 = blockIdx.x * 4, tid = threadIdx.x;
    const int ni = g_niters;
    __shared__ __align__(16) float zs[4][ND];
    __shared__ __align__(16) float red[192];

    #pragma unroll
    for (int k = 0; k < 4; ++k) {
        int t = t0 + k;
        if (tid < NX) zs[k][tid] = (t <= TH) ? states[(size_t)t * NX + tid] : 0.0f;
        else zs[k][tid] = 0.0f;
    }
    __syncthreads();

    if (tid < NU) {
        #pragma unroll
        for (int k = 0; k < 4; ++k) {
            int t = t0 + k;
            if (t < TH) {
                int r = TH - 1 - t; if (r > ni - 1) r = ni - 1;
                const float* Kr = g_Ks + (size_t)r * (NU * NX) + tid * NX;
                float a0 = 0.f, a1 = 0.f, a2 = 0.f, a3 = 0.f;
                #pragma unroll 8
                for (int j = 0; j < NX; j += 4) {
                    a0 += Kr[j    ] * zs[k][j    ];
                    a1 += Kr[j + 1] * zs[k][j + 1];
                    a2 += Kr[j + 2] * zs[k][j + 2];
                    a3 += Kr[j + 3] * zs[k][j + 3];
                }
                float u = g_ks[r * NU + tid] + (a0 + a1) + (a2 + a3);
                zs[k][NX + tid] = u;
                us[(size_t)t * NU + tid] = u;
            }
        }
    }
    __syncthreads();

    float cz0 = 0.f, cz1 = 0.f, cz2 = 0.f, cz3 = 0.f;
    #pragma unroll 4
    for (int i = 0; i < ND; ++i) {
        float Cv = C[i * ND + tid];
        cz0 += zs[0][i] * Cv;
        cz1 += zs[1][i] * Cv;
        cz2 += zs[2][i] * Cv;
        cz3 += zs[3][i] * Cv;
    }
    const float cv = c[tid];
    float val[4];
    val[0] = zs[0][tid] * (0.5f * cz0 + cv);
    val[1] = zs[1][tid] * (0.5f * cz1 + cv);
    val[2] = zs[2][tid] * (0.5f * cz2 + cv);
    val[3] = zs[3][tid] * (0.5f * cz3 + cv);

    #pragma unroll
    for (int k = 0; k < 4; ++k) {
        __syncthreads();
        red[tid] = val[k];
        __syncthreads();
        #pragma unroll
        for (int s = 96; s >= 6; s >>= 1) {
            if (tid < s) red[tid] += red[tid + s];
            __syncthreads();
        }
        int t = t0 + k;
        if (tid == 0 && t <= TH)
            costs[t] = red[0] + red[1] + red[2] + red[3] + red[4] + red[5];
    }
}

// ---------------- launch ----------------
extern "C" void kernel_launch(void* const* d_in, const int* in_sizes, int n_in,
                              void* d_out, int out_size) {
    const float* F  = (const float*)d_in[0];
    const float* f  = (const float*)d_in[1];
    const float* C  = (const float*)d_in[2];
    const float* c  = (const float*)d_in[3];
    const float* x0 = (const float*)d_in[4];
    (void)in_sizes; (void)n_in; (void)out_size;

    float* out        = (float*)d_out;
    float* out_states = out;
    float* out_us     = out + (size_t)(TH + 1) * NX;
    float* out_costs  = out_us + (size_t)TH * NU;

    cudaFuncSetAttribute(k_backward, cudaFuncAttributeMaxDynamicSharedMemorySize, SMEM_BK);

    k_setup<<<96, NT>>>(F, C, c);         // user idx 0
    k_nop<<<1, 32>>>();                   // idx 1
    k_nop<<<1, 32>>>();                   // idx 2
    k_backward<<<GB, NT, SMEM_BK>>>(F, f, C, c);   // idx 3 -> ncu capture target
    k_power<<<PB, 256>>>();
    k_heads<<<1, 256>>>(x0, out_states);
    k_fill<<<64, 256>>>(out_states);
    k_epilogue<<<(TH + 4) / 4, 192>>>(C, c, out_states, out_us, out_costs);
}

// round 16
// speedup vs baseline: 1.9717x; 1.1654x over previous
#include <cuda_runtime.h>
#include <cstdint>

#define NX 128
#define NU 64
#define ND 192
#define TH 2048
#define GB 32
#define NT 256
#define RPB 6
#define SEG 32
#define IT_SW 32
#define PB 17

// dynamic smem layout (float offsets) -- no aliasing
#define OFF_FU   0        // 128x64  F_u, staged once
#define OFF_QXU  8192     // 128x64
#define OFF_QUU  16384    // 64x64
#define OFF_X    20480    // 64x64 row-major
#define OFF_XT   24576    // 64x64 transposed
#define OFF_Y4   28672    // 4x64
#define OFF_QU   28928    // 64
#define SMEM_FLOATS 28992
#define SMEM_BK (SMEM_FLOATS * 4)

__device__ __align__(16) float g_Ft[ND * NX];
__device__ __align__(16) float g_Vb[2][NX * NX];
__device__ __align__(16) float g_vb[2][NX];
__device__ __align__(16) float g_Q[ND * ND];
__device__ __align__(16) float g_q[ND];
__device__ __align__(16) float g_invb[2][NU * NU];
__device__ __align__(16) float g_invbT[2][NU * NU];
__device__ __align__(16) float g_Ks[(size_t)TH * NU * NX];
__device__ __align__(16) float g_ks[TH * NU];
__device__ __align__(16) float g_Ms[(size_t)TH * NX * NX];
__device__ __align__(16) float g_bs[TH * NX];
__device__ __align__(16) float g_P[2][NX * NX];
__device__ __align__(16) float g_pb[2][NX];
__device__ unsigned g_delta[TH];
__device__ unsigned g_vmax[TH];
__device__ int g_niters;
__device__ unsigned g_barcnt = 0;
__device__ unsigned g_bargen = 0;
__device__ unsigned g_barcnt2 = 0;
__device__ unsigned g_bargen2 = 0;

__device__ __forceinline__ void gbar_n(unsigned* cnt, unsigned* gen_p, unsigned nb) {
    __syncthreads();
    if (threadIdx.x == 0) {
        __threadfence();
        volatile unsigned* vg = gen_p;
        unsigned gen = *vg;
        if (atomicAdd(cnt, 1u) == nb - 1) {
            *cnt = 0u;
            __threadfence();
            atomicAdd(gen_p, 1u);
        } else {
            while (*vg == gen) {}
        }
        __threadfence();
    }
    __syncthreads();
}
__device__ __forceinline__ void gbar() { gbar_n(&g_barcnt, &g_bargen, GB); }

__global__ void k_nop() {}

__global__ void __launch_bounds__(NT) k_setup(const float* __restrict__ F,
                                              const float* __restrict__ C,
                                              const float* __restrict__ c) {
    int idx = blockIdx.x * NT + threadIdx.x;
    if (idx < ND * NX) {
        int i = idx / NX, m = idx - i * NX;
        g_Ft[i * NX + m] = F[m * ND + i];
    }
    if (idx < NX * NX) {
        int i = idx >> 7, j = idx & 127;
        g_Vb[0][idx] = C[i * ND + j];
    }
    if (idx < NX) g_vb[0][idx] = c[idx];
    if (idx < TH) { g_delta[idx] = 0u; g_vmax[idx] = 0u; }
    if (idx == 0) g_niters = TH;
}

// ---------------- backward Riccati (persistent, 32 CTAs, 2 barriers/iter) ----------------
__global__ void __launch_bounds__(NT) k_backward(const float* __restrict__ F,
                                                 const float* __restrict__ f,
                                                 const float* __restrict__ C,
                                                 const float* __restrict__ c) {
    const int b = blockIdx.x, tid = threadIdx.x;
    const int jb = b * 4;          // owned K / V' / M columns
    const int c0 = b * 2;          // owned X' columns
    extern __shared__ float sm[];

    __shared__ __align__(16) float ft6[6][NX];
    __shared__ __align__(16) float fv6[6][NX];
    __shared__ __align__(16) float pf2[2 * 6 * NX];
    __shared__ __align__(16) float prAp[2][64];
    __shared__ __align__(16) float prIp[2][64];
    __shared__ __align__(16) float fshp[2][64];
    __shared__ float rmax[8], rvmx[8];
    __shared__ __align__(16) float Wsh[256];
    __shared__ __align__(16) float Zsh[256];
    __shared__ __align__(16) float ush[128];
    __shared__ __align__(16) float wqs[64];
    __shared__ __align__(16) float zqs[64];
    __shared__ __align__(16) float ksh[64];
    __shared__ __align__(16) float Ksh[256];     // [u*4 + jj]

    // stage F_u once into dynamic smem (pitch 64)
    for (int o = tid; o < 128 * 64; o += NT) {
        int i = o >> 6, u = o & 63;
        sm[OFF_FU + i * 64 + u] = F[i * ND + NX + u];
    }
    __syncthreads();

    for (int it = 0; it < TH; ++it) {
        const int p = it & 1;
        const bool newton = (it >= IT_SW);
        const float* V  = g_Vb[p];
        const float* v  = g_vb[p];
        float* Vn = g_Vb[p ^ 1];
        float* vn = g_vb[p ^ 1];
        const int i0 = b * RPB;

        // ===== phase 1: register-blocked Q build (one pass, 6 rows) =====
        for (int o = tid; o < 6 * NX; o += NT) {
            int r = o >> 7, k = o & 127;
            ft6[r][k] = g_Ft[(i0 + r) * NX + k];
        }
        __syncthreads();
        {
            const int m = tid & 127, g = tid >> 7;
            float a0 = 0.f, a1 = 0.f, a2 = 0.f, a3 = 0.f, a4 = 0.f, a5 = 0.f;
            const float* Vg = V + (g * 64) * NX + m;
            #pragma unroll 8
            for (int k = 0; k < 64; k += 4) {
                float v0 = __ldcg(Vg + (k    ) * NX);
                float v1 = __ldcg(Vg + (k + 1) * NX);
                float v2 = __ldcg(Vg + (k + 2) * NX);
                float v3 = __ldcg(Vg + (k + 3) * NX);
                #pragma unroll
                for (int r = 0; r < 6; ++r) {
                    float4 fr = *(const float4*)&ft6[r][g * 64 + k];
                    float t = fr.x * v0 + fr.y * v1 + fr.z * v2 + fr.w * v3;
                    if (r == 0) a0 += t; else if (r == 1) a1 += t;
                    else if (r == 2) a2 += t; else if (r == 3) a3 += t;
                    else if (r == 4) a4 += t; else a5 += t;
                }
            }
            pf2[g * 768 + 0 * 128 + m] = a0;
            pf2[g * 768 + 1 * 128 + m] = a1;
            pf2[g * 768 + 2 * 128 + m] = a2;
            pf2[g * 768 + 3 * 128 + m] = a3;
            pf2[g * 768 + 4 * 128 + m] = a4;
            pf2[g * 768 + 5 * 128 + m] = a5;
        }
        __syncthreads();
        {
            float* fv6f = &fv6[0][0];
            for (int o = tid; o < 768; o += NT) fv6f[o] = pf2[o] + pf2[768 + o];
        }
        __syncthreads();
        // q rows
        if (tid < 192) {
            int r = tid >> 5, lane = tid & 31;
            float s = 0.f;
            #pragma unroll
            for (int m = lane; m < 128; m += 32)
                s += fv6[r][m] * f[m] + ft6[r][m] * __ldcg(&v[m]);
            #pragma unroll
            for (int o = 16; o > 0; o >>= 1) s += __shfl_down_sync(0xffffffffu, s, o);
            if (lane == 0) g_q[i0 + r] = c[i0 + r] + s;
        }
        // Q rows (6-row register blocked over F reads)
        if (tid < ND) {
            const int j = tid;
            float acc[6];
            #pragma unroll
            for (int r = 0; r < 6; ++r) acc[r] = C[(i0 + r) * ND + j];
            #pragma unroll 4
            for (int mm = 0; mm < 128; mm += 4) {
                float s0 = F[(mm    ) * ND + j];
                float s1 = F[(mm + 1) * ND + j];
                float s2 = F[(mm + 2) * ND + j];
                float s3 = F[(mm + 3) * ND + j];
                #pragma unroll
                for (int r = 0; r < 6; ++r) {
                    float4 fr = *(const float4*)&fv6[r][mm];
                    acc[r] += fr.x * s0 + fr.y * s1 + fr.z * s2 + fr.w * s3;
                }
            }
            #pragma unroll
            for (int r = 0; r < 6; ++r) g_Q[(i0 + r) * ND + j] = acc[r];
        }
        gbar();   // barrier 1: Q ready

        // old V values for delta (f4, own 4 columns)
        float4 vold4;
        if (tid < 128) vold4 = __ldcg((const float4*)&V[tid * NX + jb]);

        // ===== bulk staging (high MLP): QXU always; QUU/X/XT for Newton =====
        #pragma unroll
        for (int o = tid; o < 2048; o += NT) {
            int row = o >> 4, c4 = o & 15;
            float4 q4v = __ldcg((const float4*)&g_Q[row * ND + NX + c4 * 4]);
            *(float4*)&sm[OFF_QXU + row * 64 + c4 * 4] = q4v;
        }
        {
            int jj = tid >> 6, m = tid & 63;
            sm[OFF_Y4 + jj * 64 + m] = __ldcg(&g_Q[(NX + m) * ND + jb + jj]);
        }
        if (b == 0 && tid < 64) sm[OFF_QU + tid] = __ldcg(&g_q[NX + tid]);
        if (newton) {
            #pragma unroll
            for (int o = tid; o < 1024; o += NT) {
                int row = o >> 4, c4 = o & 15;
                float4 q4v = __ldcg((const float4*)&g_Q[(NX + row) * ND + NX + c4 * 4]);
                *(float4*)&sm[OFF_QUU + row * 64 + c4 * 4] = q4v;
            }
            #pragma unroll
            for (int o = tid; o < 1024; o += NT) {
                float4 x4 = __ldcg((const float4*)&g_invb[p][o * 4]);
                *(float4*)&sm[OFF_X + o * 4] = x4;
            }
            #pragma unroll
            for (int o = tid; o < 1024; o += NT) {
                float4 x4 = __ldcg((const float4*)&g_invbT[p][o * 4]);
                *(float4*)&sm[OFF_XT + o * 4] = x4;
            }
        }

        // ===== produce X (row) + Xt (transposed) in smem (GJ path) =====
        if (!newton) {
            // register Gauss-Jordan, every CTA; ONE sync per pivot (parity buffers)
            const int r = tid >> 2, q4 = tid & 3;
            float ar[16], vi[16];
            #pragma unroll
            for (int jq = 0; jq < 4; ++jq) {
                float4 a4 = __ldcg((const float4*)&g_Q[(NX + r) * ND + NX + q4 * 16 + jq * 4]);
                ar[jq * 4 + 0] = a4.x; ar[jq * 4 + 1] = a4.y;
                ar[jq * 4 + 2] = a4.z; ar[jq * 4 + 3] = a4.w;
            }
            #pragma unroll
            for (int jj = 0; jj < 16; ++jj) vi[jj] = (q4 * 16 + jj == r) ? 1.0f : 0.0f;

            #pragma unroll 1
            for (int pv = 0; pv < 64; ++pv) {
                const int ps = pv >> 4, pj = pv & 15, par = pv & 1;
                float apj = ar[pj];
                float pivv = __shfl_sync(0xffffffffu, apj, (pv * 4 + ps) & 31);
                if (q4 == ps) fshp[par][r] = apj;
                if (r == pv) {
                    float rcp = 1.0f / pivv;
                    #pragma unroll
                    for (int jj = 0; jj < 16; ++jj) {
                        ar[jj] *= rcp; vi[jj] *= rcp;
                        prAp[par][q4 * 16 + jj] = ar[jj];
                        prIp[par][q4 * 16 + jj] = vi[jj];
                    }
                }
                __syncthreads();
                if (r != pv) {
                    const float fr = fshp[par][r];
                    #pragma unroll
                    for (int jj = 0; jj < 16; ++jj) {
                        ar[jj] = fmaf(-fr, prAp[par][q4 * 16 + jj], ar[jj]);
                        vi[jj] = fmaf(-fr, prIp[par][q4 * 16 + jj], vi[jj]);
                    }
                }
            }
            #pragma unroll
            for (int jj = 0; jj < 16; ++jj) {
                int col = q4 * 16 + jj;
                sm[OFF_X  + r * 64 + col] = vi[jj];
                sm[OFF_XT + col * 64 + r] = vi[jj];
                if (b == 0) {
                    g_invb[p ^ 1][r * 64 + col]  = vi[jj];
                    g_invbT[p ^ 1][col * 64 + r] = vi[jj];
                }
            }
        }
        __syncthreads();

        // ===== S1: W = X y ; b0: wq = X qu =====
        {
            int u = tid & 63, jj = tid >> 6;
            float s = 0.f;
            #pragma unroll 4
            for (int mq = 0; mq < 64; mq += 4) {
                float4 x4 = *(const float4*)&sm[OFF_X + u * 64 + mq];
                float4 y4 = *(const float4*)&sm[OFF_Y4 + jj * 64 + mq];
                s += x4.x * y4.x + x4.y * y4.y + x4.z * y4.z + x4.w * y4.w;
            }
            Wsh[jj * 64 + u] = s;
            if (b == 0 && tid < 64) {
                float t = 0.f;
                #pragma unroll 4
                for (int mq = 0; mq < 64; mq += 4) {
                    float4 x4 = *(const float4*)&sm[OFF_X + tid * 64 + mq];
                    float4 q4 = *(const float4*)&sm[OFF_QU + mq];
                    t += x4.x * q4.x + x4.y * q4.y + x4.z * q4.z + x4.w * q4.w;
                }
                wqs[tid] = t;
            }
        }
        __syncthreads();

        if (!newton) {
            // K = -W, k = -wq
            int u = tid & 63, jj = tid >> 6;
            float kv = -Wsh[jj * 64 + u];
            Ksh[u * 4 + jj] = kv;
            g_Ks[(size_t)it * (NU * NX) + u * NX + jb + jj] = kv;
            if (b == 0 && tid < 64) ksh[tid] = -wqs[tid];
        } else {
            // S2: Z = Quu W ; ush = Quu x_cc ; b0: zq = Quu wq
            {
                int r = tid & 63, jj = tid >> 6;
                float s = 0.f;
                #pragma unroll 4
                for (int mq = 0; mq < 64; mq += 4) {
                    float4 q4 = *(const float4*)&sm[OFF_QUU + r * 64 + mq];
                    float4 w4 = *(const float4*)&Wsh[jj * 64 + mq];
                    s += q4.x * w4.x + q4.y * w4.y + q4.z * w4.z + q4.w * w4.w;
                }
                Zsh[jj * 64 + r] = s;
                if (tid < 128) {
                    int rr = tid & 63, ci = tid >> 6, cc = c0 + ci;
                    float t = 0.f;
                    #pragma unroll 4
                    for (int mq = 0; mq < 64; mq += 4) {
                        float4 q4 = *(const float4*)&sm[OFF_QUU + rr * 64 + mq];
                        float4 x4 = *(const float4*)&sm[OFF_XT + cc * 64 + mq];
                        t += q4.x * x4.x + q4.y * x4.y + q4.z * x4.z + q4.w * x4.w;
                    }
                    ush[ci * 64 + rr] = t;
                }
                if (b == 0 && tid < 64) {
                    float t = 0.f;
                    #pragma unroll 4
                    for (int mq = 0; mq < 64; mq += 4) {
                        float4 q4 = *(const float4*)&sm[OFF_QUU + tid * 64 + mq];
                        float4 w4 = *(const float4*)&wqs[mq];
                        t += q4.x * w4.x + q4.y * w4.y + q4.z * w4.z + q4.w * w4.w;
                    }
                    zqs[tid] = t;
                }
            }
            __syncthreads();
            // S3: K = -(2W - X Z) ; X' = 2X - X ush ; b0: k
            {
                int u = tid & 63, jj = tid >> 6;
                float s = 0.f;
                #pragma unroll 4
                for (int mq = 0; mq < 64; mq += 4) {
                    float4 x4 = *(const float4*)&sm[OFF_X + u * 64 + mq];
                    float4 z4 = *(const float4*)&Zsh[jj * 64 + mq];
                    s += x4.x * z4.x + x4.y * z4.y + x4.z * z4.z + x4.w * z4.w;
                }
                float kv = -(2.0f * Wsh[jj * 64 + u] - s);
                Ksh[u * 4 + jj] = kv;
                g_Ks[(size_t)it * (NU * NX) + u * NX + jb + jj] = kv;
                if (tid < 128) {
                    int rr = tid & 63, ci = tid >> 6, cc = c0 + ci;
                    float t = 0.f;
                    #pragma unroll 4
                    for (int mq = 0; mq < 64; mq += 4) {
                        float4 x4 = *(const float4*)&sm[OFF_X + rr * 64 + mq];
                        float4 u4 = *(const float4*)&ush[ci * 64 + mq];
                        t += x4.x * u4.x + x4.y * u4.y + x4.z * u4.z + x4.w * u4.w;
                    }
                    float xn = 2.0f * sm[OFF_X + rr * 64 + cc] - t;
                    g_invb[p ^ 1][rr * 64 + cc]  = xn;
                    g_invbT[p ^ 1][cc * 64 + rr] = xn;
                }
                if (b == 0 && tid < 64) {
                    float t = 0.f;
                    #pragma unroll 4
                    for (int mq = 0; mq < 64; mq += 4) {
                        float4 x4 = *(const float4*)&sm[OFF_X + tid * 64 + mq];
                        float4 z4 = *(const float4*)&zqs[mq];
                        t += x4.x * z4.x + x4.y * z4.y + x4.z * z4.z + x4.w * z4.w;
                    }
                    ksh[tid] = -(2.0f * wqs[tid] - t);
                }
            }
        }
        __syncthreads();

        // ===== V' (t<128) and M (t>=128), 4 columns each; v', b; delta =====
        {
            float dmax = 0.f, vmx = 0.f;
            const int i = tid & 127;
            const bool doM = tid >= 128;
            const int base = (doM ? OFF_FU : OFF_QXU) + i * 64;
            float a0 = 0.f, a1 = 0.f, a2 = 0.f, a3 = 0.f;
            #pragma unroll 4
            for (int uq = 0; uq < 64; uq += 4) {
                float4 s4 = *(const float4*)&sm[base + uq];
                float4 k0 = *(const float4*)&Ksh[(uq    ) * 4];
                float4 k1 = *(const float4*)&Ksh[(uq + 1) * 4];
                float4 k2 = *(const float4*)&Ksh[(uq + 2) * 4];
                float4 k3 = *(const float4*)&Ksh[(uq + 3) * 4];
                a0 += s4.x * k0.x + s4.y * k1.x + s4.z * k2.x + s4.w * k3.x;
                a1 += s4.x * k0.y + s4.y * k1.y + s4.z * k2.y + s4.w * k3.y;
                a2 += s4.x * k0.z + s4.y * k1.z + s4.z * k2.z + s4.w * k3.z;
                a3 += s4.x * k0.w + s4.y * k1.w + s4.z * k2.w + s4.w * k3.w;
            }
            if (!doM) {
                float4 qx = __ldcg((const float4*)&g_Q[i * ND + jb]);
                float4 vnewv;
                vnewv.x = qx.x + a0; vnewv.y = qx.y + a1;
                vnewv.z = qx.z + a2; vnewv.w = qx.w + a3;
                *(float4*)&Vn[i * NX + jb] = vnewv;
                dmax = fmaxf(fmaxf(fabsf(vnewv.x - vold4.x), fabsf(vnewv.y - vold4.y)),
                             fmaxf(fabsf(vnewv.z - vold4.z), fabsf(vnewv.w - vold4.w)));
                vmx  = fmaxf(fmaxf(fabsf(vnewv.x), fabsf(vnewv.y)),
                             fmaxf(fabsf(vnewv.z), fabsf(vnewv.w)));
            } else {
                float4 fx;
                fx.x = F[i * ND + jb    ];
                fx.y = F[i * ND + jb + 1];
                fx.z = F[i * ND + jb + 2];
                fx.w = F[i * ND + jb + 3];
                float4 mv;
                mv.x = fx.x + a0; mv.y = fx.y + a1;
                mv.z = fx.z + a2; mv.w = fx.w + a3;
                *(float4*)&g_Ms[(size_t)it * (NX * NX) + i * NX + jb] = mv;
            }
            if (b == 0) {
                float s = 0.f, sb = 0.f;
                #pragma unroll 4
                for (int uq = 0; uq < 64; uq += 4) {
                    float4 k4 = *(const float4*)&ksh[uq];
                    float4 qx4 = *(const float4*)&sm[OFF_QXU + i * 64 + uq];
                    float4 fu4 = *(const float4*)&sm[OFF_FU + i * 64 + uq];
                    s  += qx4.x * k4.x + qx4.y * k4.y + qx4.z * k4.z + qx4.w * k4.w;
                    sb += fu4.x * k4.x + fu4.y * k4.y + fu4.z * k4.z + fu4.w * k4.w;
                }
                if (!doM) {
                    vn[i] = __ldcg(&g_q[i]) + s;
                    g_bs[it * NX + i] = f[i] + sb;
                    if (i < NU) g_ks[it * NU + i] = ksh[i];
                }
            }
            #pragma unroll
            for (int o = 16; o > 0; o >>= 1) {
                dmax = fmaxf(dmax, __shfl_down_sync(0xffffffffu, dmax, o));
                vmx  = fmaxf(vmx,  __shfl_down_sync(0xffffffffu, vmx, o));
            }
            if ((tid & 31) == 0) { rmax[tid >> 5] = dmax; rvmx[tid >> 5] = vmx; }
            __syncthreads();
            if (tid == 0) {
                float d = rmax[0], vv = rvmx[0];
                #pragma unroll
                for (int w = 1; w < 8; ++w) { d = fmaxf(d, rmax[w]); vv = fmaxf(vv, rvmx[w]); }
                atomicMax(&g_delta[it], __float_as_uint(d));
                atomicMax(&g_vmax[it], __float_as_uint(vv));
            }
        }
        gbar();   // barrier 2: end of iteration

        {
            float dd = __uint_as_float(__ldcg(&g_delta[it]));
            float vv = __uint_as_float(__ldcg(&g_vmax[it]));
            if (dd <= 2.5e-6f * vv) {
                if (b == 0 && tid == 0) g_niters = it + 1;
                break;
            }
        }
    }
}

// ---------------- persistent power kernel: copy + 5 affine squarings ----------------
__global__ void __launch_bounds__(256) k_power() {
    const int tid = threadIdx.x;
    {
        const int ni = g_niters;
        const float* src = g_Ms + (size_t)(ni - 1) * (NX * NX);
        for (int o = blockIdx.x * 256 + tid; o < NX * NX; o += PB * 256)
            g_P[0][o] = __ldcg(&src[o]);
        if (blockIdx.x == 16 && tid < NX) g_pb[0][tid] = __ldcg(&g_bs[(ni - 1) * NX + tid]);
    }
    gbar_n(&g_barcnt2, &g_bargen2, PB);

    __shared__ __align__(16) float As[32][33];
    __shared__ __align__(16) float Bs[32][33];
    #pragma unroll 1
    for (int s = 0; s < 5; ++s) {
        const int p = s & 1;
        const float* Ms = g_P[p];
        const float* bs = g_pb[p];
        float* Md = g_P[p ^ 1];
        float* bd = g_pb[p ^ 1];

        if (blockIdx.x == 16) {
            if (tid < NX) {
                float s0 = 0.f, s1 = 0.f;
                #pragma unroll 8
                for (int k = 0; k < NX; k += 2) {
                    s0 += __ldcg(&Ms[tid * NX + k    ]) * __ldcg(&bs[k    ]);
                    s1 += __ldcg(&Ms[tid * NX + k + 1]) * __ldcg(&bs[k + 1]);
                }
                bd[tid] = (s0 + s1) + __ldcg(&bs[tid]);
            }
        } else {
            const int tr = blockIdx.x >> 2, tc = blockIdx.x & 3;
            const int r  = tid >> 3;
            const int c4 = (tid & 7) * 4;
            float acc0 = 0.f, acc1 = 0.f, acc2 = 0.f, acc3 = 0.f;
            for (int kb = 0; kb < 4; ++kb) {
                #pragma unroll
                for (int l = tid; l < 1024; l += 256) {
                    int lr = l >> 5, lc = l & 31;
                    As[lr][lc] = __ldcg(&Ms[(tr * 32 + lr) * NX + kb * 32 + lc]);
                    Bs[lr][lc] = __ldcg(&Ms[(kb * 32 + lr) * NX + tc * 32 + lc]);
                }
                __syncthreads();
                #pragma unroll
                for (int k = 0; k < 32; ++k) {
                    float av = As[r][k];
                    acc0 += av * Bs[k][c4    ];
                    acc1 += av * Bs[k][c4 + 1];
                    acc2 += av * Bs[k][c4 + 2];
                    acc3 += av * Bs[k][c4 + 3];
                }
                __syncthreads();
            }
            float* dst = Md + (size_t)(tr * 32 + r) * NX + tc * 32 + c4;
            dst[0] = acc0; dst[1] = acc1; dst[2] = acc2; dst[3] = acc3;
        }
        gbar_n(&g_barcnt2, &g_bargen2, PB);
    }
}

// ---------------- segment heads (M^32 chain) + time-varying tail ----------------
__global__ void __launch_bounds__(256) k_heads(const float* __restrict__ x0,
                                               float* __restrict__ out_states) {
    const int tid = threadIdx.x;
    const int row = tid & 127, half = tid >> 7;
    const int ni = g_niters;
    const int tconv = TH - ni;
    const int NS = (tconv + 1) / SEG;
    __shared__ __align__(16) float xs[NX];
    __shared__ __align__(16) float ps[256];

    float mreg[64];
    {
        const float* Mc = g_P[1] + row * NX + half * 64;
        #pragma unroll
        for (int j = 0; j < 64; j += 4) {
            float4 t4 = *(const float4*)(Mc + j);
            mreg[j] = t4.x; mreg[j + 1] = t4.y; mreg[j + 2] = t4.z; mreg[j + 3] = t4.w;
        }
    }
    float breg = g_pb[1][row];

    if (tid < NX) { xs[tid] = x0[tid]; out_states[tid] = x0[tid]; }
    __syncthreads();

    for (int s = 1; s <= NS; ++s) {
        float a0 = 0.f, a1 = 0.f, a2 = 0.f, a3 = 0.f;
        #pragma unroll
        for (int j = 0; j < 64; j += 4) {
            a0 += mreg[j    ] * xs[half * 64 + j    ];
            a1 += mreg[j + 1] * xs[half * 64 + j + 1];
            a2 += mreg[j + 2] * xs[half * 64 + j + 2];
            a3 += mreg[j + 3] * xs[half * 64 + j + 3];
        }
        ps[tid] = (a0 + a1) + (a2 + a3);
        __syncthreads();
        if (half == 0) {
            float xn = ps[row] + ps[128 + row] + breg;
            xs[row] = xn;
            out_states[(size_t)s * SEG * NX + row] = xn;
        }
        __syncthreads();
    }

    {
        const float* Mc = g_Ms + (size_t)(ni - 1) * (NX * NX) + row * NX + half * 64;
        #pragma unroll
        for (int j = 0; j < 64; j += 4) {
            float4 t4 = *(const float4*)(Mc + j);
            mreg[j] = t4.x; mreg[j + 1] = t4.y; mreg[j + 2] = t4.z; mreg[j + 3] = t4.w;
        }
        breg = g_bs[(ni - 1) * NX + row];
    }
    for (int t = NS * SEG; t < TH; ++t) {
        if (t > tconv) {
            const int r = TH - 1 - t;
            const float* Mr = g_Ms + (size_t)r * (NX * NX) + row * NX + half * 64;
            #pragma unroll
            for (int j = 0; j < 64; j += 4) {
                float4 t4 = *(const float4*)(Mr + j);
                mreg[j] = t4.x; mreg[j + 1] = t4.y; mreg[j + 2] = t4.z; mreg[j + 3] = t4.w;
            }
            breg = g_bs[r * NX + row];
        }
        float a0 = 0.f, a1 = 0.f, a2 = 0.f, a3 = 0.f;
        #pragma unroll
        for (int j = 0; j < 64; j += 4) {
            a0 += mreg[j    ] * xs[half * 64 + j    ];
            a1 += mreg[j + 1] * xs[half * 64 + j + 1];
            a2 += mreg[j + 2] * xs[half * 64 + j + 2];
            a3 += mreg[j + 3] * xs[half * 64 + j + 3];
        }
        ps[tid] = (a0 + a1) + (a2 + a3);
        __syncthreads();
        if (half == 0) {
            float xn = ps[row] + ps[128 + row] + breg;
            xs[row] = xn;
            out_states[(size_t)(t + 1) * NX + row] = xn;
        }
        __syncthreads();
    }
}

// ---------------- parallel segment fill ----------------
__global__ void __launch_bounds__(256) k_fill(float* __restrict__ out_states) {
    const int s = blockIdx.x;
    const int tid = threadIdx.x;
    const int row = tid & 127, half = tid >> 7;
    const int ni = g_niters;
    const int tconv = TH - ni;
    const int NS = (tconv + 1) / SEG;
    if (s >= NS) return;
    __shared__ __align__(16) float xs[NX];
    __shared__ __align__(16) float ps[256];

    float mreg[64];
    {
        const float* Mc = g_Ms + (size_t)(ni - 1) * (NX * NX) + row * NX + half * 64;
        #pragma unroll
        for (int j = 0; j < 64; j += 4) {
            float4 t4 = *(const float4*)(Mc + j);
            mreg[j] = t4.x; mreg[j + 1] = t4.y; mreg[j + 2] = t4.z; mreg[j + 3] = t4.w;
        }
    }
    float breg = g_bs[(ni - 1) * NX + row];

    if (tid < NX) xs[tid] = out_states[(size_t)s * SEG * NX + tid];
    __syncthreads();

    #pragma unroll 1
    for (int j2 = 1; j2 < SEG; ++j2) {
        float a0 = 0.f, a1 = 0.f, a2 = 0.f, a3 = 0.f;
        #pragma unroll
        for (int j = 0; j < 64; j += 4) {
            a0 += mreg[j    ] * xs[half * 64 + j    ];
            a1 += mreg[j + 1] * xs[half * 64 + j + 1];
            a2 += mreg[j + 2] * xs[half * 64 + j + 2];
            a3 += mreg[j + 3] * xs[half * 64 + j + 3];
        }
        ps[tid] = (a0 + a1) + (a2 + a3);
        __syncthreads();
        if (half == 0) {
            float xn = ps[row] + ps[128 + row] + breg;
            xs[row] = xn;
            out_states[(size_t)(s * SEG + j2) * NX + row] = xn;
        }
        __syncthreads();
    }
}

// ---------------- epilogue: 4 timesteps per block ----------------
__global__ void __launch_bounds__(192) k_epilogue(const float* __restrict__ C,
                                                  const float* __restrict__ c,
                                                  const float* __restrict__ states,
                                                  float* __restrict__ us,
                                                  float* __restrict__ costs) {
    const int t0 = blockIdx.x * 4, tid = threadIdx.x;
    const int ni = g_niters;
    __shared__ __align__(16) float zs[4][ND];
    __shared__ __align__(16) float red[192];

    #pragma unroll
    for (int k = 0; k < 4; ++k) {
        int t = t0 + k;
        if (tid < NX) zs[k][tid] = (t <= TH) ? states[(size_t)t * NX + tid] : 0.0f;
        else zs[k][tid] = 0.0f;
    }
    __syncthreads();

    if (tid < NU) {
        #pragma unroll
        for (int k = 0; k < 4; ++k) {
            int t = t0 + k;
            if (t < TH) {
                int r = TH - 1 - t; if (r > ni - 1) r = ni - 1;
                const float* Kr = g_Ks + (size_t)r * (NU * NX) + tid * NX;
                float a0 = 0.f, a1 = 0.f, a2 = 0.f, a3 = 0.f;
                #pragma unroll 8
                for (int j = 0; j < NX; j += 4) {
                    a0 += Kr[j    ] * zs[k][j    ];
                    a1 += Kr[j + 1] * zs[k][j + 1];
                    a2 += Kr[j + 2] * zs[k][j + 2];
                    a3 += Kr[j + 3] * zs[k][j + 3];
                }
                float u = g_ks[r * NU + tid] + (a0 + a1) + (a2 + a3);
                zs[k][NX + tid] = u;
                us[(size_t)t * NU + tid] = u;
            }
        }
    }
    __syncthreads();

    float cz0 = 0.f, cz1 = 0.f, cz2 = 0.f, cz3 = 0.f;
    #pragma unroll 4
    for (int i = 0; i < ND; ++i) {
        float Cv = C[i * ND + tid];
        cz0 += zs[0][i] * Cv;
        cz1 += zs[1][i] * Cv;
        cz2 += zs[2][i] * Cv;
        cz3 += zs[3][i] * Cv;
    }
    const float cv = c[tid];
    float val[4];
    val[0] = zs[0][tid] * (0.5f * cz0 + cv);
    val[1] = zs[1][tid] * (0.5f * cz1 + cv);
    val[2] = zs[2][tid] * (0.5f * cz2 + cv);
    val[3] = zs[3][tid] * (0.5f * cz3 + cv);

    #pragma unroll
    for (int k = 0; k < 4; ++k) {
        __syncthreads();
        red[tid] = val[k];
        __syncthreads();
        #pragma unroll
        for (int s = 96; s >= 6; s >>= 1) {
            if (tid < s) red[tid] += red[tid + s];
            __syncthreads();
        }
        int t = t0 + k;
        if (tid == 0 && t <= TH)
            costs[t] = red[0] + red[1] + red[2] + red[3] + red[4] + red[5];
    }
}

// ---------------- launch ----------------
extern "C" void kernel_launch(void* const* d_in, const int* in_sizes, int n_in,
                              void* d_out, int out_size) {
    const float* F  = (const float*)d_in[0];
    const float* f  = (const float*)d_in[1];
    const float* C  = (const float*)d_in[2];
    const float* c  = (const float*)d_in[3];
    const float* x0 = (const float*)d_in[4];
    (void)in_sizes; (void)n_in; (void)out_size;

    float* out        = (float*)d_out;
    float* out_states = out;
    float* out_us     = out + (size_t)(TH + 1) * NX;
    float* out_costs  = out_us + (size_t)TH * NU;

    cudaFuncSetAttribute(k_backward, cudaFuncAttributeMaxDynamicSharedMemorySize, SMEM_BK);

    k_setup<<<96, NT>>>(F, C, c);         // user idx 0
    k_nop<<<1, 32>>>();                   // idx 1
    k_nop<<<1, 32>>>();                   // idx 2
    k_backward<<<GB, NT, SMEM_BK>>>(F, f, C, c);   // idx 3 -> ncu capture target
    k_power<<<PB, 256>>>();
    k_heads<<<1, 256>>>(x0, out_states);
    k_fill<<<64, 256>>>(out_states);
    k_epilogue<<<(TH + 4) / 4, 192>>>(C, c, out_states, out_us, out_costs);
}